// round 2
// baseline (speedup 1.0000x reference)
#include <cuda_runtime.h>
#include <math.h>

// Problem dims
#define NB   8
#define NL   1024
#define NC   1024
#define NH   8
#define NCH  128
#define NBH  64           // NB*NH
#define N3C  3072
#define QK_SCALE 0.29730177875068026f  // 128^(-1/4)

// Scratch (allocation-free rule: __device__ globals)
__device__ float g_xn  [(size_t)NB * NL * NC];        // 32 MB
__device__ float g_qkv [(size_t)NB * NL * N3C];       // 96 MB
__device__ float g_attn[(size_t)NB * NL * NC];        // 32 MB

// ---------------------------------------------------------------------------
// LayerNorm: one block per row (8192 rows x 1024 ch), 256 threads, float4
// ---------------------------------------------------------------------------
__global__ void __launch_bounds__(256) ln_kernel(
    const float* __restrict__ x, const float* __restrict__ gamma,
    const float* __restrict__ beta, float* __restrict__ xn)
{
    int row = blockIdx.x;
    int t   = threadIdx.x;
    const float4* xr = reinterpret_cast<const float4*>(x + (size_t)row * NC);
    float4 v = xr[t];
    float s  = v.x + v.y + v.z + v.w;
    float ss = v.x*v.x + v.y*v.y + v.z*v.z + v.w*v.w;
    #pragma unroll
    for (int o = 16; o; o >>= 1) {
        s  += __shfl_xor_sync(0xffffffffu, s,  o);
        ss += __shfl_xor_sync(0xffffffffu, ss, o);
    }
    __shared__ float rs[8], rss[8], stat[2];
    int warp = t >> 5, lane = t & 31;
    if (lane == 0) { rs[warp] = s; rss[warp] = ss; }
    __syncthreads();
    if (t == 0) {
        float a = 0.f, b2 = 0.f;
        #pragma unroll
        for (int i = 0; i < 8; i++) { a += rs[i]; b2 += rss[i]; }
        float mu  = a * (1.0f / NC);
        float var = b2 * (1.0f / NC) - mu * mu;
        stat[0] = mu;
        stat[1] = rsqrtf(var + 1e-5f);
    }
    __syncthreads();
    float mu = stat[0], rstd = stat[1];
    float4 g4 = reinterpret_cast<const float4*>(gamma)[t];
    float4 b4 = reinterpret_cast<const float4*>(beta )[t];
    float4 o;
    o.x = (v.x - mu) * rstd * g4.x + b4.x;
    o.y = (v.y - mu) * rstd * g4.y + b4.y;
    o.z = (v.z - mu) * rstd * g4.z + b4.z;
    o.w = (v.w - mu) * rstd * g4.w + b4.w;
    reinterpret_cast<float4*>(xn + (size_t)row * NC)[t] = o;
}

// ---------------------------------------------------------------------------
// SGEMM 128x128 tile, BK=8, 256 threads, 8x8 microtile.
// MODE 0: C = (A@B + bias) * (col<2048 ? QK_SCALE : 1)      [QKV proj]
// MODE 1: C = A@B + bias + resid                             [out proj + residual]
// ---------------------------------------------------------------------------
template <int MODE>
__global__ void __launch_bounds__(256, 1) sgemm_kernel(
    const float* __restrict__ A, const float* __restrict__ Bw,
    const float* __restrict__ bias, const float* __restrict__ resid,
    float* __restrict__ Cm, int M, int N, int K)
{
    __shared__ float As[8][128];
    __shared__ float Bs[8][128];
    int tid = threadIdx.x;
    int tr = tid >> 4, tc = tid & 15;
    const int bm = blockIdx.y * 128;
    const int bn = blockIdx.x * 128;
    int arow = tid >> 1;
    int acol = (tid & 1) << 2;
    int brow = tid >> 5;
    int bcol = (tid & 31) << 2;
    const float* Ag = A  + (size_t)(bm + arow) * K + acol;
    const float* Bg = Bw + (size_t)brow * N + bn + bcol;

    float acc[8][8];
    #pragma unroll
    for (int i = 0; i < 8; i++)
        #pragma unroll
        for (int j = 0; j < 8; j++) acc[i][j] = 0.f;

    for (int kk = 0; kk < K; kk += 8) {
        float4 av = *(const float4*)(Ag + kk);
        float4 bv = *(const float4*)(Bg + (size_t)kk * N);
        __syncthreads();
        As[acol + 0][arow] = av.x;
        As[acol + 1][arow] = av.y;
        As[acol + 2][arow] = av.z;
        As[acol + 3][arow] = av.w;
        *(float4*)&Bs[brow][bcol] = bv;
        __syncthreads();
        #pragma unroll
        for (int k = 0; k < 8; k++) {
            float a[8], b[8];
            *(float4*)&a[0] = *(const float4*)&As[k][tr * 4];
            *(float4*)&a[4] = *(const float4*)&As[k][tr * 4 + 64];
            *(float4*)&b[0] = *(const float4*)&Bs[k][tc * 4];
            *(float4*)&b[4] = *(const float4*)&Bs[k][tc * 4 + 64];
            #pragma unroll
            for (int i = 0; i < 8; i++)
                #pragma unroll
                for (int j = 0; j < 8; j++)
                    acc[i][j] += a[i] * b[j];
        }
    }

    #pragma unroll
    for (int i = 0; i < 8; i++) {
        int r = bm + tr * 4 + (i & 3) + ((i >> 2) << 6);
        #pragma unroll
        for (int jh = 0; jh < 2; jh++) {
            int cbase = bn + tc * 4 + jh * 64;
            float4 bb = *(const float4*)&bias[cbase];
            float4 o;
            o.x = acc[i][jh * 4 + 0] + bb.x;
            o.y = acc[i][jh * 4 + 1] + bb.y;
            o.z = acc[i][jh * 4 + 2] + bb.z;
            o.w = acc[i][jh * 4 + 3] + bb.w;
            if (MODE == 0) {
                float m = (cbase < 2 * NC) ? QK_SCALE : 1.0f;
                o.x *= m; o.y *= m; o.z *= m; o.w *= m;
            } else {
                float4 rr = *(const float4*)&resid[(size_t)r * NC + cbase];
                o.x += rr.x; o.y += rr.y; o.z += rr.z; o.w += rr.w;
            }
            *(float4*)&Cm[(size_t)r * N + cbase] = o;
        }
    }
}

// ---------------------------------------------------------------------------
// Flash attention on the RAW-RESHAPED layout. 64 "bh" batches, L=1024, d=128.
// BM=128 query tile, BN=128 kv tile. 256 threads = 32(tr) x 8(tc).
// S frag: rows tr*4+i (i<4), cols tc+8j (j<16). O frag: same rows, cols tc*4+32m(+t).
// K/V share one smem buffer; Q and K swizzled (xor on float4 index) for
// conflict-free LDS.128; V unswizzled (row-uniform reads are conflict-free).
// ---------------------------------------------------------------------------
#define SWZ(r) ((((r) & 7) ^ (((r) >> 3) & 7)))
#define PS_STRIDE 130
#define ATT_SMEM_FLOATS (128 * 128 * 2 + 128 * PS_STRIDE)

__global__ void __launch_bounds__(256, 1) attn_kernel(
    const float* __restrict__ qkv, float* __restrict__ outp)
{
    extern __shared__ float sm[];
    float* Qs  = sm;                  // 128x128 swizzled
    float* KVs = Qs + 128 * 128;      // 128x128 (K swizzled, then V plain)
    float* Ps  = KVs + 128 * 128;     // 128 x PS_STRIDE

    int tid = threadIdx.x;
    int bh  = blockIdx.y;
    int m0  = blockIdx.x * 128;
    int bb  = bh >> 3, hh = bh & 7;
    const float* base = qkv + (size_t)(bb * 1024 + hh * 128) * N3C;

    // Load Q tile (raw-reshape gather): row l2 -> gmem row h*128+(l2>>3), col (l2&7)*128+c
    #pragma unroll
    for (int i = 0; i < 16; i++) {
        int f = i * 256 + tid;
        int r = f >> 5, c4 = f & 31;
        int l2 = m0 + r;
        const float* src = base + (size_t)(l2 >> 3) * N3C + ((l2 & 7) << 7) + (c4 << 2);
        *(float4*)&Qs[r * 128 + ((c4 ^ SWZ(r)) << 2)] = *(const float4*)src;
    }

    int tr = tid >> 3, tc = tid & 7;
    float o[4][16];
    float mprev[4], lsum[4];
    #pragma unroll
    for (int i = 0; i < 4; i++) {
        mprev[i] = -3.0e38f; lsum[i] = 0.f;
        #pragma unroll
        for (int j = 0; j < 16; j++) o[i][j] = 0.f;
    }

    for (int kt = 0; kt < 8; kt++) {
        int n0 = kt * 128;
        __syncthreads();  // prior O-phase done with KVs/Ps; Q stores (first iter)
        // Load K tile (swizzled)
        #pragma unroll
        for (int i = 0; i < 16; i++) {
            int f = i * 256 + tid;
            int r = f >> 5, c4 = f & 31;
            int n = n0 + r;
            const float* src = base + (size_t)(n >> 3) * N3C + NC + ((n & 7) << 7) + (c4 << 2);
            *(float4*)&KVs[r * 128 + ((c4 ^ SWZ(r)) << 2)] = *(const float4*)src;
        }
        __syncthreads();

        // S = Q K^T, 4x16 fragment per thread
        float s[4][16];
        #pragma unroll
        for (int i = 0; i < 4; i++)
            #pragma unroll
            for (int j = 0; j < 16; j++) s[i][j] = 0.f;
        #pragma unroll 4
        for (int d4 = 0; d4 < 32; d4++) {
            float4 a[4];
            #pragma unroll
            for (int i = 0; i < 4; i++) {
                int r = tr * 4 + i;
                a[i] = *(const float4*)&Qs[r * 128 + ((d4 ^ SWZ(r)) << 2)];
            }
            #pragma unroll
            for (int j = 0; j < 16; j++) {
                int c = tc + (j << 3);
                float4 b = *(const float4*)&KVs[c * 128 + ((d4 ^ SWZ(c)) << 2)];
                #pragma unroll
                for (int i = 0; i < 4; i++)
                    s[i][j] += a[i].x * b.x + a[i].y * b.y + a[i].z * b.z + a[i].w * b.w;
            }
        }
        __syncthreads();  // all warps done reading K from KVs

        // Stream V gmem->smem (plain layout), overwriting K
        #pragma unroll 4
        for (int i = 0; i < 16; i++) {
            int f = i * 256 + tid;
            int r = f >> 5, c4 = f & 31;
            int n = n0 + r;
            const float* src = base + (size_t)(n >> 3) * N3C + 2 * NC + ((n & 7) << 7) + (c4 << 2);
            *(float4*)&KVs[r * 128 + (c4 << 2)] = *(const float4*)src;
        }

        // Online softmax (row reduction across the 8 tc lanes of each row)
        #pragma unroll
        for (int i = 0; i < 4; i++) {
            float mx = s[i][0];
            #pragma unroll
            for (int j = 1; j < 16; j++) mx = fmaxf(mx, s[i][j]);
            mx = fmaxf(mx, __shfl_xor_sync(0xffffffffu, mx, 1));
            mx = fmaxf(mx, __shfl_xor_sync(0xffffffffu, mx, 2));
            mx = fmaxf(mx, __shfl_xor_sync(0xffffffffu, mx, 4));
            float mnew = fmaxf(mprev[i], mx);
            float ls = 0.f;
            #pragma unroll
            for (int j = 0; j < 16; j++) {
                s[i][j] = __expf(s[i][j] - mnew);
                ls += s[i][j];
            }
            ls += __shfl_xor_sync(0xffffffffu, ls, 1);
            ls += __shfl_xor_sync(0xffffffffu, ls, 2);
            ls += __shfl_xor_sync(0xffffffffu, ls, 4);
            float alpha = __expf(mprev[i] - mnew);
            lsum[i] = lsum[i] * alpha + ls;
            mprev[i] = mnew;
            #pragma unroll
            for (int j = 0; j < 16; j++) o[i][j] *= alpha;
        }

        // Store P fragment
        #pragma unroll
        for (int i = 0; i < 4; i++) {
            int r = tr * 4 + i;
            #pragma unroll
            for (int j = 0; j < 16; j++)
                Ps[r * PS_STRIDE + tc + (j << 3)] = s[i][j];
        }
        __syncthreads();  // V + P visible

        // O += P @ V
        #pragma unroll 2
        for (int c = 0; c < 128; c++) {
            float p[4];
            #pragma unroll
            for (int i = 0; i < 4; i++) p[i] = Ps[(tr * 4 + i) * PS_STRIDE + c];
            float4 vv[4];
            #pragma unroll
            for (int m = 0; m < 4; m++)
                vv[m] = *(const float4*)&KVs[c * 128 + ((tc + (m << 3)) << 2)];
            #pragma unroll
            for (int i = 0; i < 4; i++)
                #pragma unroll
                for (int m = 0; m < 4; m++) {
                    o[i][m * 4 + 0] += p[i] * vv[m].x;
                    o[i][m * 4 + 1] += p[i] * vv[m].y;
                    o[i][m * 4 + 2] += p[i] * vv[m].z;
                    o[i][m * 4 + 3] += p[i] * vv[m].w;
                }
        }
    }

    // Normalize and write out (flat layout == raw reshape back to [B,L,C])
    #pragma unroll
    for (int i = 0; i < 4; i++) {
        float inv = 1.0f / lsum[i];
        int r = m0 + tr * 4 + i;
        float* dst = outp + (size_t)bh * (NL * NCH) + (size_t)r * NCH;
        #pragma unroll
        for (int m = 0; m < 4; m++) {
            float4 w;
            w.x = o[i][m * 4 + 0] * inv;
            w.y = o[i][m * 4 + 1] * inv;
            w.z = o[i][m * 4 + 2] * inv;
            w.w = o[i][m * 4 + 3] * inv;
            *(float4*)&dst[tc * 4 + (m << 5)] = w;
        }
    }
}

// ---------------------------------------------------------------------------
extern "C" void kernel_launch(void* const* d_in, const int* in_sizes, int n_in,
                              void* d_out, int out_size)
{
    const float* x     = (const float*)d_in[0];
    const float* ln_g  = (const float*)d_in[1];
    const float* ln_b  = (const float*)d_in[2];
    const float* w_qkv = (const float*)d_in[3];
    const float* b_qkv = (const float*)d_in[4];
    const float* w_out = (const float*)d_in[5];
    const float* b_out = (const float*)d_in[6];
    float* out = (float*)d_out;

    float *xn, *qkvb, *attnb;
    cudaGetSymbolAddress((void**)&xn,    g_xn);
    cudaGetSymbolAddress((void**)&qkvb,  g_qkv);
    cudaGetSymbolAddress((void**)&attnb, g_attn);

    // 1) LayerNorm
    ln_kernel<<<NB * NL, 256>>>(x, ln_g, ln_b, xn);

    // 2) QKV projection (+bias, q/k scaled)
    sgemm_kernel<0><<<dim3(N3C / 128, (NB * NL) / 128), 256>>>(
        xn, w_qkv, b_qkv, nullptr, qkvb, NB * NL, N3C, NC);

    // 3) Attention on raw-reshaped heads
    static const size_t att_smem = (size_t)ATT_SMEM_FLOATS * sizeof(float);
    cudaFuncSetAttribute(attn_kernel, cudaFuncAttributeMaxDynamicSharedMemorySize,
                         (int)att_smem);
    attn_kernel<<<dim3(NL / 128, NBH), 256, att_smem>>>(qkvb, attnb);

    // 4) Output projection + bias + residual(xn)
    sgemm_kernel<1><<<dim3(NC / 128, (NB * NL) / 128), 256>>>(
        attnb, w_out, b_out, xn, out, NB * NL, NC, NC);
}

// round 6
// speedup vs baseline: 1.7589x; 1.7589x over previous
#include <cuda_runtime.h>
#include <cstdint>
#include <math.h>

// Problem dims
#define NB   8
#define NL   1024
#define NC   1024
#define NH   8
#define NCH  128
#define NBH  64
#define N3C  3072
#define QK_SCALE 0.29730177875068026f  // 128^(-1/4)

// Scratch (allocation-free rule: __device__ globals)
__device__ float g_xn   [(size_t)NB * NL * NC];
__device__ float g_qkv  [(size_t)NB * NL * N3C];
__device__ float g_attn [(size_t)NB * NL * NC];
__device__ float g_wqkvT[(size_t)N3C * NC];   // w_qkv^T  [3C, C]
__device__ float g_woutT[(size_t)NC * NC];    // w_out^T  [C, C]

// ---------------------------------------------------------------------------
// Helpers (sm_80+ PTX only; target is plain compute_103 — no 'a' features!)
// ---------------------------------------------------------------------------
__device__ __forceinline__ uint32_t smem_u32(const void* p) {
    uint32_t a;
    asm("{ .reg .u64 t; cvta.to.shared.u64 t, %1; cvt.u32.u64 %0, t; }" : "=r"(a) : "l"(p));
    return a;
}
__device__ __forceinline__ void cp16(uint32_t dst, const void* src) {
    asm volatile("cp.async.cg.shared.global [%0], [%1], 16;" :: "r"(dst), "l"(src));
}
#define CP_COMMIT() asm volatile("cp.async.commit_group;" ::: "memory")
#define CP_WAIT(n)  asm volatile("cp.async.wait_group %0;" :: "n"(n) : "memory")

__device__ __forceinline__ void mma_tf32(float* d, const uint32_t* a, const uint32_t* b) {
    asm volatile("mma.sync.aligned.m16n8k8.row.col.f32.tf32.tf32.f32 "
        "{%0,%1,%2,%3}, {%4,%5,%6,%7}, {%8,%9}, {%0,%1,%2,%3};"
        : "+f"(d[0]), "+f"(d[1]), "+f"(d[2]), "+f"(d[3])
        : "r"(a[0]), "r"(a[1]), "r"(a[2]), "r"(a[3]), "r"(b[0]), "r"(b[1]));
}

// ---------------------------------------------------------------------------
// LayerNorm (verified)
// ---------------------------------------------------------------------------
__global__ void __launch_bounds__(256) ln_kernel(
    const float* __restrict__ x, const float* __restrict__ gamma,
    const float* __restrict__ beta, float* __restrict__ xn)
{
    int row = blockIdx.x;
    int t   = threadIdx.x;
    const float4* xr = reinterpret_cast<const float4*>(x + (size_t)row * NC);
    float4 v = xr[t];
    float s  = v.x + v.y + v.z + v.w;
    float ss = v.x*v.x + v.y*v.y + v.z*v.z + v.w*v.w;
    #pragma unroll
    for (int o = 16; o; o >>= 1) {
        s  += __shfl_xor_sync(0xffffffffu, s,  o);
        ss += __shfl_xor_sync(0xffffffffu, ss, o);
    }
    __shared__ float rs[8], rss[8], stat[2];
    int warp = t >> 5, lane = t & 31;
    if (lane == 0) { rs[warp] = s; rss[warp] = ss; }
    __syncthreads();
    if (t == 0) {
        float a = 0.f, b2 = 0.f;
        #pragma unroll
        for (int i = 0; i < 8; i++) { a += rs[i]; b2 += rss[i]; }
        float mu  = a * (1.0f / NC);
        float var = b2 * (1.0f / NC) - mu * mu;
        stat[0] = mu;
        stat[1] = rsqrtf(var + 1e-5f);
    }
    __syncthreads();
    float mu = stat[0], rstd = stat[1];
    float4 g4 = reinterpret_cast<const float4*>(gamma)[t];
    float4 b4 = reinterpret_cast<const float4*>(beta )[t];
    float4 o;
    o.x = (v.x - mu) * rstd * g4.x + b4.x;
    o.y = (v.y - mu) * rstd * g4.y + b4.y;
    o.z = (v.z - mu) * rstd * g4.z + b4.z;
    o.w = (v.w - mu) * rstd * g4.w + b4.w;
    reinterpret_cast<float4*>(xn + (size_t)row * NC)[t] = o;
}

// ---------------------------------------------------------------------------
// 32x32 tiled transpose
// ---------------------------------------------------------------------------
__global__ void __launch_bounds__(256) transpose_kernel(
    const float* __restrict__ src, float* __restrict__ dst, int R, int Ccols)
{
    __shared__ float t[32][33];
    int bx = blockIdx.x * 32, by = blockIdx.y * 32;
    #pragma unroll
    for (int i = 0; i < 4; i++)
        t[threadIdx.y + i * 8][threadIdx.x] =
            src[(size_t)(by + threadIdx.y + i * 8) * Ccols + bx + threadIdx.x];
    __syncthreads();
    #pragma unroll
    for (int i = 0; i < 4; i++)
        dst[(size_t)(bx + threadIdx.y + i * 8) * R + by + threadIdx.x] =
            t[threadIdx.x][threadIdx.y + i * 8];
}

// ---------------------------------------------------------------------------
// tf32 mma.sync GEMM:  C[M,N] = A[M,K] @ BT[N,K]^T (+bias; MODE epilogue)
// CTA 128x128, BK=32, 8 warps = 2(M)x4(N), warp tile 64x32 (4x4 m16n8k8).
// SMEM rows padded to stride 36 floats -> conflict-free fragment LDS.
// 2-stage cp.async double buffer. MODE 0: q/k scale. MODE 1: +resid.
// ---------------------------------------------------------------------------
#define BM 128
#define BN 128
#define BK 32
#define KTOT 1024
#define NCHUNK (KTOT / BK)
#define ASTRIDE 36
#define SMA (BM * ASTRIDE)          // floats
#define SMB (BN * ASTRIDE)
#define SMEM_GEMM ((SMA + SMB) * 2 * 4)   // 73728 bytes

template <int MODE>
__global__ void __launch_bounds__(256) gemm_mma_kernel(
    const float* __restrict__ A, const float* __restrict__ BT,
    const float* __restrict__ bias, const float* __restrict__ resid,
    float* __restrict__ Cm, int N)
{
    extern __shared__ float smf[];
    uint32_t sbase = smem_u32(smf);
    int tid = threadIdx.x;
    int wid = tid >> 5, lane = tid & 31;
    int g = lane >> 2, q = lane & 3;
    const int bm = blockIdx.y * BM;
    const int bn = blockIdx.x * BN;
    const int warpM = (wid >> 2) * 64;
    const int warpN = (wid & 3) * 32;

    // buffer layout: [A0][B0][A1][B1]
    auto offA = [&](int buf) { return buf * (SMA + SMB); };
    auto offB = [&](int buf) { return buf * (SMA + SMB) + SMA; };

    // async-load one BK chunk (A:128x32, B:128x32) into buffer
    int r_ld = tid >> 1;                 // 0..127
    int c4_ld = (tid & 1) << 2;          // 0 or 4 (two float4 per row handled by i-loop)
    auto load_chunk = [&](int kk, int buf) {
        #pragma unroll
        for (int i = 0; i < 4; i++) {    // 1024 float4 ops for A / 256 thr = 4
            int f = i * 256 + tid;
            int r = f >> 3, c4 = (f & 7) << 2;
            cp16(sbase + (offA(buf) + r * ASTRIDE + c4) * 4,
                 A + (size_t)(bm + r) * KTOT + kk + c4);
        }
        #pragma unroll
        for (int i = 0; i < 4; i++) {
            int f = i * 256 + tid;
            int r = f >> 3, c4 = (f & 7) << 2;
            cp16(sbase + (offB(buf) + r * ASTRIDE + c4) * 4,
                 BT + (size_t)(bn + r) * KTOT + kk + c4);
        }
        CP_COMMIT();
    };
    (void)r_ld; (void)c4_ld;

    float acc[2][4][4];   // [mt][nt][reg]  (2 m-tiles of 16 x warp has 4... see below)
    // warp tile 64x32 => 4 m-tiles x 4 n-tiles; acc[4][4][4] = 64 regs
    float accf[4][4][4];
    #pragma unroll
    for (int mt = 0; mt < 4; mt++)
        #pragma unroll
        for (int nt = 0; nt < 4; nt++)
            #pragma unroll
            for (int r = 0; r < 4; r++) accf[mt][nt][r] = 0.f;
    (void)acc;

    load_chunk(0, 0);
    load_chunk(BK, 1);

    for (int c = 0; c < NCHUNK; c++) {
        if (c + 1 < NCHUNK) CP_WAIT(1); else CP_WAIT(0);
        __syncthreads();
        const float* As = smf + offA(c & 1);
        const float* Bs = smf + offB(c & 1);
        #pragma unroll
        for (int ks = 0; ks < 4; ks++) {
            int k0 = ks * 8;
            uint32_t afr[4][4], bfr[4][2];
            #pragma unroll
            for (int mt = 0; mt < 4; mt++) {
                const float* ap = As + (warpM + mt * 16 + g) * ASTRIDE + k0 + q;
                afr[mt][0] = __float_as_uint(ap[0]);
                afr[mt][1] = __float_as_uint(ap[8 * ASTRIDE]);
                afr[mt][2] = __float_as_uint(ap[4]);
                afr[mt][3] = __float_as_uint(ap[8 * ASTRIDE + 4]);
            }
            #pragma unroll
            for (int nt = 0; nt < 4; nt++) {
                const float* bp = Bs + (warpN + nt * 8 + g) * ASTRIDE + k0 + q;
                bfr[nt][0] = __float_as_uint(bp[0]);
                bfr[nt][1] = __float_as_uint(bp[4]);
            }
            #pragma unroll
            for (int mt = 0; mt < 4; mt++)
                #pragma unroll
                for (int nt = 0; nt < 4; nt++)
                    mma_tf32(accf[mt][nt], afr[mt], bfr[nt]);
        }
        __syncthreads();
        if (c + 2 < NCHUNK) load_chunk((c + 2) * BK, c & 1);
    }

    // Epilogue: c0,c1 -> (row g, col 2q+{0,1}); c2,c3 -> row g+8
    #pragma unroll
    for (int mt = 0; mt < 4; mt++) {
        int row0 = bm + warpM + mt * 16 + g;
        #pragma unroll
        for (int nt = 0; nt < 4; nt++) {
            int col = bn + warpN + nt * 8 + q * 2;
            float2 bb = *(const float2*)&bias[col];
            float mscale = 1.0f;
            if (MODE == 0) mscale = (col < 2 * NC) ? QK_SCALE : 1.0f;
            #pragma unroll
            for (int h = 0; h < 2; h++) {
                int row = row0 + h * 8;
                float2 o;
                o.x = accf[mt][nt][h * 2 + 0] + bb.x;
                o.y = accf[mt][nt][h * 2 + 1] + bb.y;
                if (MODE == 0) { o.x *= mscale; o.y *= mscale; }
                else {
                    float2 rr = *(const float2*)&resid[(size_t)row * NC + col];
                    o.x += rr.x; o.y += rr.y;
                }
                *(float2*)&Cm[(size_t)row * N + col] = o;
            }
        }
    }
}

// ---------------------------------------------------------------------------
// Flash attention on RAW-RESHAPED layout (verified, unchanged)
// ---------------------------------------------------------------------------
#define SWZ(r) ((((r) & 7) ^ (((r) >> 3) & 7)))
#define PS_STRIDE 130
#define ATT_SMEM_FLOATS (128 * 128 * 2 + 128 * PS_STRIDE)

__global__ void __launch_bounds__(256, 1) attn_kernel(
    const float* __restrict__ qkv, float* __restrict__ outp)
{
    extern __shared__ float smf[];
    float* Qs  = smf;
    float* KVs = Qs + 128 * 128;
    float* Ps  = KVs + 128 * 128;

    int tid = threadIdx.x;
    int bh  = blockIdx.y;
    int m0  = blockIdx.x * 128;
    int bb  = bh >> 3, hh = bh & 7;
    const float* base = qkv + (size_t)(bb * 1024 + hh * 128) * N3C;

    #pragma unroll
    for (int i = 0; i < 16; i++) {
        int f = i * 256 + tid;
        int r = f >> 5, c4 = f & 31;
        int l2 = m0 + r;
        const float* src = base + (size_t)(l2 >> 3) * N3C + ((l2 & 7) << 7) + (c4 << 2);
        *(float4*)&Qs[r * 128 + ((c4 ^ SWZ(r)) << 2)] = *(const float4*)src;
    }

    int tr = tid >> 3, tc = tid & 7;
    float o[4][16];
    float mprev[4], lsum[4];
    #pragma unroll
    for (int i = 0; i < 4; i++) {
        mprev[i] = -3.0e38f; lsum[i] = 0.f;
        #pragma unroll
        for (int j = 0; j < 16; j++) o[i][j] = 0.f;
    }

    for (int kt = 0; kt < 8; kt++) {
        int n0 = kt * 128;
        __syncthreads();
        #pragma unroll
        for (int i = 0; i < 16; i++) {
            int f = i * 256 + tid;
            int r = f >> 5, c4 = f & 31;
            int n = n0 + r;
            const float* src = base + (size_t)(n >> 3) * N3C + NC + ((n & 7) << 7) + (c4 << 2);
            *(float4*)&KVs[r * 128 + ((c4 ^ SWZ(r)) << 2)] = *(const float4*)src;
        }
        __syncthreads();

        float s[4][16];
        #pragma unroll
        for (int i = 0; i < 4; i++)
            #pragma unroll
            for (int j = 0; j < 16; j++) s[i][j] = 0.f;
        #pragma unroll 4
        for (int d4 = 0; d4 < 32; d4++) {
            float4 a[4];
            #pragma unroll
            for (int i = 0; i < 4; i++) {
                int r = tr * 4 + i;
                a[i] = *(const float4*)&Qs[r * 128 + ((d4 ^ SWZ(r)) << 2)];
            }
            #pragma unroll
            for (int j = 0; j < 16; j++) {
                int c = tc + (j << 3);
                float4 b = *(const float4*)&KVs[c * 128 + ((d4 ^ SWZ(c)) << 2)];
                #pragma unroll
                for (int i = 0; i < 4; i++)
                    s[i][j] += a[i].x * b.x + a[i].y * b.y + a[i].z * b.z + a[i].w * b.w;
            }
        }
        __syncthreads();

        #pragma unroll 4
        for (int i = 0; i < 16; i++) {
            int f = i * 256 + tid;
            int r = f >> 5, c4 = f & 31;
            int n = n0 + r;
            const float* src = base + (size_t)(n >> 3) * N3C + 2 * NC + ((n & 7) << 7) + (c4 << 2);
            *(float4*)&KVs[r * 128 + (c4 << 2)] = *(const float4*)src;
        }

        #pragma unroll
        for (int i = 0; i < 4; i++) {
            float mx = s[i][0];
            #pragma unroll
            for (int j = 1; j < 16; j++) mx = fmaxf(mx, s[i][j]);
            mx = fmaxf(mx, __shfl_xor_sync(0xffffffffu, mx, 1));
            mx = fmaxf(mx, __shfl_xor_sync(0xffffffffu, mx, 2));
            mx = fmaxf(mx, __shfl_xor_sync(0xffffffffu, mx, 4));
            float mnew = fmaxf(mprev[i], mx);
            float ls = 0.f;
            #pragma unroll
            for (int j = 0; j < 16; j++) {
                s[i][j] = __expf(s[i][j] - mnew);
                ls += s[i][j];
            }
            ls += __shfl_xor_sync(0xffffffffu, ls, 1);
            ls += __shfl_xor_sync(0xffffffffu, ls, 2);
            ls += __shfl_xor_sync(0xffffffffu, ls, 4);
            float alpha = __expf(mprev[i] - mnew);
            lsum[i] = lsum[i] * alpha + ls;
            mprev[i] = mnew;
            #pragma unroll
            for (int j = 0; j < 16; j++) o[i][j] *= alpha;
        }

        #pragma unroll
        for (int i = 0; i < 4; i++) {
            int r = tr * 4 + i;
            #pragma unroll
            for (int j = 0; j < 16; j++)
                Ps[r * PS_STRIDE + tc + (j << 3)] = s[i][j];
        }
        __syncthreads();

        #pragma unroll 2
        for (int c = 0; c < 128; c++) {
            float p[4];
            #pragma unroll
            for (int i = 0; i < 4; i++) p[i] = Ps[(tr * 4 + i) * PS_STRIDE + c];
            float4 vv[4];
            #pragma unroll
            for (int m = 0; m < 4; m++)
                vv[m] = *(const float4*)&KVs[c * 128 + ((tc + (m << 3)) << 2)];
            #pragma unroll
            for (int i = 0; i < 4; i++)
                #pragma unroll
                for (int m = 0; m < 4; m++) {
                    o[i][m * 4 + 0] += p[i] * vv[m].x;
                    o[i][m * 4 + 1] += p[i] * vv[m].y;
                    o[i][m * 4 + 2] += p[i] * vv[m].z;
                    o[i][m * 4 + 3] += p[i] * vv[m].w;
                }
        }
    }

    #pragma unroll
    for (int i = 0; i < 4; i++) {
        float inv = 1.0f / lsum[i];
        int r = m0 + tr * 4 + i;
        float* dst = outp + (size_t)bh * (NL * NCH) + (size_t)r * NCH;
        #pragma unroll
        for (int m = 0; m < 4; m++) {
            float4 w;
            w.x = o[i][m * 4 + 0] * inv;
            w.y = o[i][m * 4 + 1] * inv;
            w.z = o[i][m * 4 + 2] * inv;
            w.w = o[i][m * 4 + 3] * inv;
            *(float4*)&dst[tc * 4 + (m << 5)] = w;
        }
    }
}

// ---------------------------------------------------------------------------
extern "C" void kernel_launch(void* const* d_in, const int* in_sizes, int n_in,
                              void* d_out, int out_size)
{
    const float* x     = (const float*)d_in[0];
    const float* ln_g  = (const float*)d_in[1];
    const float* ln_b  = (const float*)d_in[2];
    const float* w_qkv = (const float*)d_in[3];
    const float* b_qkv = (const float*)d_in[4];
    const float* w_out = (const float*)d_in[5];
    const float* b_out = (const float*)d_in[6];
    float* out = (float*)d_out;

    float *xn, *qkvb, *attnb, *wqkvT, *woutT;
    cudaGetSymbolAddress((void**)&xn,    g_xn);
    cudaGetSymbolAddress((void**)&qkvb,  g_qkv);
    cudaGetSymbolAddress((void**)&attnb, g_attn);
    cudaGetSymbolAddress((void**)&wqkvT, g_wqkvT);
    cudaGetSymbolAddress((void**)&woutT, g_woutT);

    cudaFuncSetAttribute(gemm_mma_kernel<0>,
                         cudaFuncAttributeMaxDynamicSharedMemorySize, SMEM_GEMM);
    cudaFuncSetAttribute(gemm_mma_kernel<1>,
                         cudaFuncAttributeMaxDynamicSharedMemorySize, SMEM_GEMM);
    static const size_t att_smem = (size_t)ATT_SMEM_FLOATS * sizeof(float);
    cudaFuncSetAttribute(attn_kernel, cudaFuncAttributeMaxDynamicSharedMemorySize,
                         (int)att_smem);

    // 0) Transpose weights to [N, K] (K-major per output column)
    transpose_kernel<<<dim3(N3C / 32, NC / 32), dim3(32, 8)>>>(w_qkv, wqkvT, NC, N3C);
    transpose_kernel<<<dim3(NC / 32,  NC / 32), dim3(32, 8)>>>(w_out, woutT, NC, NC);

    // 1) LayerNorm
    ln_kernel<<<NB * NL, 256>>>(x, ln_g, ln_b, xn);

    // 2) QKV projection (tf32 mma.sync; +bias, q/k scaled)
    gemm_mma_kernel<0><<<dim3(N3C / BN, (NB * NL) / BM), 256, SMEM_GEMM>>>(
        xn, wqkvT, b_qkv, nullptr, qkvb, N3C);

    // 3) Attention on raw-reshaped heads
    attn_kernel<<<dim3(NL / 128, NBH), 256, att_smem>>>(qkvb, attnb);

    // 4) Output projection + bias + residual(xn)  (tf32 mma.sync)
    gemm_mma_kernel<1><<<dim3(NC / BN, (NB * NL) / BM), 256, SMEM_GEMM>>>(
        attnb, woutT, b_out, xn, out, NC);
}

// round 8
// speedup vs baseline: 3.2059x; 1.8227x over previous
#include <cuda_runtime.h>
#include <cstdint>
#include <math.h>

// Problem dims
#define NB   8
#define NL   1024
#define NC   1024
#define NH   8
#define NCH  128
#define NBH  64
#define N3C  3072
#define QK_SCALE 0.29730177875068026f  // 128^(-1/4)
#define LOG2E    1.4426950408889634f

// Scratch (allocation-free rule: __device__ globals)
__device__ float g_xn   [(size_t)NB * NL * NC];
__device__ float g_qkv  [(size_t)NB * NL * N3C];
__device__ float g_attn [(size_t)NB * NL * NC];
__device__ float g_wqkvT[(size_t)N3C * NC];
__device__ float g_woutT[(size_t)NC * NC];

// ---------------------------------------------------------------------------
// Helpers (sm_80+ PTX only; target is plain compute_103 — no 'a' features)
// ---------------------------------------------------------------------------
__device__ __forceinline__ uint32_t smem_u32(const void* p) {
    uint32_t a;
    asm("{ .reg .u64 t; cvta.to.shared.u64 t, %1; cvt.u32.u64 %0, t; }" : "=r"(a) : "l"(p));
    return a;
}
__device__ __forceinline__ void cp16(uint32_t dst, const void* src) {
    asm volatile("cp.async.cg.shared.global [%0], [%1], 16;" :: "r"(dst), "l"(src));
}
#define CP_COMMIT() asm volatile("cp.async.commit_group;" ::: "memory")
#define CP_WAIT(n)  asm volatile("cp.async.wait_group %0;" :: "n"(n) : "memory")

__device__ __forceinline__ void mma_tf32(float* d, const uint32_t* a, const uint32_t* b) {
    asm volatile("mma.sync.aligned.m16n8k8.row.col.f32.tf32.tf32.f32 "
        "{%0,%1,%2,%3}, {%4,%5,%6,%7}, {%8,%9}, {%0,%1,%2,%3};"
        : "+f"(d[0]), "+f"(d[1]), "+f"(d[2]), "+f"(d[3])
        : "r"(a[0]), "r"(a[1]), "r"(a[2]), "r"(a[3]), "r"(b[0]), "r"(b[1]));
}
__device__ __forceinline__ float ex2(float x) {
    float r;
    asm("ex2.approx.f32 %0, %1;" : "=f"(r) : "f"(x));
    return r;
}

// ---------------------------------------------------------------------------
// LayerNorm (verified)
// ---------------------------------------------------------------------------
__global__ void __launch_bounds__(256) ln_kernel(
    const float* __restrict__ x, const float* __restrict__ gamma,
    const float* __restrict__ beta, float* __restrict__ xn)
{
    int row = blockIdx.x;
    int t   = threadIdx.x;
    const float4* xr = reinterpret_cast<const float4*>(x + (size_t)row * NC);
    float4 v = xr[t];
    float s  = v.x + v.y + v.z + v.w;
    float ss = v.x*v.x + v.y*v.y + v.z*v.z + v.w*v.w;
    #pragma unroll
    for (int o = 16; o; o >>= 1) {
        s  += __shfl_xor_sync(0xffffffffu, s,  o);
        ss += __shfl_xor_sync(0xffffffffu, ss, o);
    }
    __shared__ float rs[8], rss[8], stat[2];
    int warp = t >> 5, lane = t & 31;
    if (lane == 0) { rs[warp] = s; rss[warp] = ss; }
    __syncthreads();
    if (t == 0) {
        float a = 0.f, b2 = 0.f;
        #pragma unroll
        for (int i = 0; i < 8; i++) { a += rs[i]; b2 += rss[i]; }
        float mu  = a * (1.0f / NC);
        float var = b2 * (1.0f / NC) - mu * mu;
        stat[0] = mu;
        stat[1] = rsqrtf(var + 1e-5f);
    }
    __syncthreads();
    float mu = stat[0], rstd = stat[1];
    float4 g4 = reinterpret_cast<const float4*>(gamma)[t];
    float4 b4 = reinterpret_cast<const float4*>(beta )[t];
    float4 o;
    o.x = (v.x - mu) * rstd * g4.x + b4.x;
    o.y = (v.y - mu) * rstd * g4.y + b4.y;
    o.z = (v.z - mu) * rstd * g4.z + b4.z;
    o.w = (v.w - mu) * rstd * g4.w + b4.w;
    reinterpret_cast<float4*>(xn + (size_t)row * NC)[t] = o;
}

// ---------------------------------------------------------------------------
// 32x32 tiled transpose
// ---------------------------------------------------------------------------
__global__ void __launch_bounds__(256) transpose_kernel(
    const float* __restrict__ src, float* __restrict__ dst, int R, int Ccols)
{
    __shared__ float t[32][33];
    int bx = blockIdx.x * 32, by = blockIdx.y * 32;
    #pragma unroll
    for (int i = 0; i < 4; i++)
        t[threadIdx.y + i * 8][threadIdx.x] =
            src[(size_t)(by + threadIdx.y + i * 8) * Ccols + bx + threadIdx.x];
    __syncthreads();
    #pragma unroll
    for (int i = 0; i < 4; i++)
        dst[(size_t)(bx + threadIdx.y + i * 8) * R + by + threadIdx.x] =
            t[threadIdx.x][threadIdx.y + i * 8];
}

// ---------------------------------------------------------------------------
// tf32 mma.sync GEMM (verified): C = A @ BT^T (+bias; MODE epilogue)
// MODE 0: q cols *= QK_SCALE*LOG2E, k cols *= QK_SCALE.  MODE 1: += resid.
// ---------------------------------------------------------------------------
#define BM 128
#define BN 128
#define BK 32
#define KTOT 1024
#define NCHUNK (KTOT / BK)
#define ASTRIDE 36
#define SMA (BM * ASTRIDE)
#define SMB (BN * ASTRIDE)
#define SMEM_GEMM ((SMA + SMB) * 2 * 4)

template <int MODE>
__global__ void __launch_bounds__(256) gemm_mma_kernel(
    const float* __restrict__ A, const float* __restrict__ BT,
    const float* __restrict__ bias, const float* __restrict__ resid,
    float* __restrict__ Cm, int N)
{
    extern __shared__ float smf[];
    uint32_t sbase = smem_u32(smf);
    int tid = threadIdx.x;
    int wid = tid >> 5, lane = tid & 31;
    int g = lane >> 2, q = lane & 3;
    const int bm = blockIdx.y * BM;
    const int bn = blockIdx.x * BN;
    const int warpM = (wid >> 2) * 64;
    const int warpN = (wid & 3) * 32;

    auto offA = [&](int buf) { return buf * (SMA + SMB); };
    auto offB = [&](int buf) { return buf * (SMA + SMB) + SMA; };

    auto load_chunk = [&](int kk, int buf) {
        #pragma unroll
        for (int i = 0; i < 4; i++) {
            int f = i * 256 + tid;
            int r = f >> 3, c4 = (f & 7) << 2;
            cp16(sbase + (offA(buf) + r * ASTRIDE + c4) * 4,
                 A + (size_t)(bm + r) * KTOT + kk + c4);
        }
        #pragma unroll
        for (int i = 0; i < 4; i++) {
            int f = i * 256 + tid;
            int r = f >> 3, c4 = (f & 7) << 2;
            cp16(sbase + (offB(buf) + r * ASTRIDE + c4) * 4,
                 BT + (size_t)(bn + r) * KTOT + kk + c4);
        }
        CP_COMMIT();
    };

    float accf[4][4][4];
    #pragma unroll
    for (int mt = 0; mt < 4; mt++)
        #pragma unroll
        for (int nt = 0; nt < 4; nt++)
            #pragma unroll
            for (int r = 0; r < 4; r++) accf[mt][nt][r] = 0.f;

    load_chunk(0, 0);
    load_chunk(BK, 1);

    for (int c = 0; c < NCHUNK; c++) {
        if (c + 1 < NCHUNK) CP_WAIT(1); else CP_WAIT(0);
        __syncthreads();
        const float* As = smf + offA(c & 1);
        const float* Bs = smf + offB(c & 1);
        #pragma unroll
        for (int ks = 0; ks < 4; ks++) {
            int k0 = ks * 8;
            uint32_t afr[4][4], bfr[4][2];
            #pragma unroll
            for (int mt = 0; mt < 4; mt++) {
                const float* ap = As + (warpM + mt * 16 + g) * ASTRIDE + k0 + q;
                afr[mt][0] = __float_as_uint(ap[0]);
                afr[mt][1] = __float_as_uint(ap[8 * ASTRIDE]);
                afr[mt][2] = __float_as_uint(ap[4]);
                afr[mt][3] = __float_as_uint(ap[8 * ASTRIDE + 4]);
            }
            #pragma unroll
            for (int nt = 0; nt < 4; nt++) {
                const float* bp = Bs + (warpN + nt * 8 + g) * ASTRIDE + k0 + q;
                bfr[nt][0] = __float_as_uint(bp[0]);
                bfr[nt][1] = __float_as_uint(bp[4]);
            }
            #pragma unroll
            for (int mt = 0; mt < 4; mt++)
                #pragma unroll
                for (int nt = 0; nt < 4; nt++)
                    mma_tf32(accf[mt][nt], afr[mt], bfr[nt]);
        }
        __syncthreads();
        if (c + 2 < NCHUNK) load_chunk((c + 2) * BK, c & 1);
    }

    #pragma unroll
    for (int mt = 0; mt < 4; mt++) {
        int row0 = bm + warpM + mt * 16 + g;
        #pragma unroll
        for (int nt = 0; nt < 4; nt++) {
            int col = bn + warpN + nt * 8 + q * 2;
            float2 bb = *(const float2*)&bias[col];
            float mscale = 1.0f;
            if (MODE == 0)
                mscale = (col < NC) ? (QK_SCALE * LOG2E)
                                    : ((col < 2 * NC) ? QK_SCALE : 1.0f);
            #pragma unroll
            for (int h = 0; h < 2; h++) {
                int row = row0 + h * 8;
                float2 o;
                o.x = accf[mt][nt][h * 2 + 0] + bb.x;
                o.y = accf[mt][nt][h * 2 + 1] + bb.y;
                if (MODE == 0) { o.x *= mscale; o.y *= mscale; }
                else {
                    float2 rr = *(const float2*)&resid[(size_t)row * NC + col];
                    o.x += rr.x; o.y += rr.y;
                }
                *(float2*)&Cm[(size_t)row * N + col] = o;
            }
        }
    }
}

// ---------------------------------------------------------------------------
// tf32 mma.sync flash attention on RAW-RESHAPED layout, no-max softmax in
// log2 domain (Q pre-scaled by log2e in QKV epilogue; S only feeds softmax).
// BMa=64 q-rows, BNa=64 kv-rows, d=128. 128 threads = 4 warps x 16 rows.
// 2 CTAs/SM (85KB smem). Sacc[8][4] (16x64), Oacc[16][4] (16x128).
// ---------------------------------------------------------------------------
#define BMA 64
#define BNA 64
#define ATS 132            // Q/KV smem stride (conflict-free frag LDS)
#define PST 68             // P smem stride
#define QOFF  0
#define KVOFF (BMA * ATS)
#define PSOFF (KVOFF + BNA * ATS)
#define ATT_SMEM ((PSOFF + BMA * PST) * 4)   // 84992 B

__global__ void __launch_bounds__(128, 2) attn_kernel(
    const float* __restrict__ qkv, float* __restrict__ outp)
{
    extern __shared__ float smf[];
    float* Qs = smf + QOFF;
    float* KVs = smf + KVOFF;
    float* Ps = smf + PSOFF;

    int tid = threadIdx.x;
    int wid = tid >> 5, lane = tid & 31;
    int g = lane >> 2, q = lane & 3;
    int bh  = blockIdx.y;
    int m0  = blockIdx.x * BMA;
    int bb  = bh >> 3, hh = bh & 7;
    const float* base = qkv + (size_t)(bb * 1024 + hh * 128) * N3C;
    const int warpM = wid * 16;

    // Load Q tile (raw-reshape gather): 64 rows x 32 float4
    #pragma unroll
    for (int i = 0; i < 16; i++) {
        int f = i * 128 + tid;
        int r = f >> 5, c4 = f & 31;
        int l2 = m0 + r;
        const float* src = base + (size_t)(l2 >> 3) * N3C + ((l2 & 7) << 7) + (c4 << 2);
        *(float4*)&Qs[r * ATS + (c4 << 2)] = *(const float4*)src;
    }

    float Oacc[16][4];
    float lsum[2] = {0.f, 0.f};
    #pragma unroll
    for (int nt = 0; nt < 16; nt++)
        #pragma unroll
        for (int r = 0; r < 4; r++) Oacc[nt][r] = 0.f;

    for (int kt = 0; kt < NL / BNA; kt++) {
        int n0 = kt * BNA;
        __syncthreads();   // prev PV done with KVs/Ps; Q visible (1st iter)

        // K tile -> KVs (rows n, cols d)
        #pragma unroll
        for (int i = 0; i < 16; i++) {
            int f = i * 128 + tid;
            int r = f >> 5, c4 = f & 31;
            int n = n0 + r;
            const float* src = base + (size_t)(n >> 3) * N3C + NC + ((n & 7) << 7) + (c4 << 2);
            *(float4*)&KVs[r * ATS + (c4 << 2)] = *(const float4*)src;
        }
        __syncthreads();

        // S = Q K^T : 16 ksteps over d=128
        float Sacc[8][4];
        #pragma unroll
        for (int nt = 0; nt < 8; nt++)
            #pragma unroll
            for (int r = 0; r < 4; r++) Sacc[nt][r] = 0.f;
        #pragma unroll
        for (int ks = 0; ks < 16; ks++) {
            int k0 = ks * 8;
            uint32_t afr[4], bfr[8][2];
            const float* ap = Qs + (warpM + g) * ATS + k0 + q;
            afr[0] = __float_as_uint(ap[0]);
            afr[1] = __float_as_uint(ap[8 * ATS]);
            afr[2] = __float_as_uint(ap[4]);
            afr[3] = __float_as_uint(ap[8 * ATS + 4]);
            #pragma unroll
            for (int nt = 0; nt < 8; nt++) {
                const float* bp = KVs + (nt * 8 + g) * ATS + k0 + q;
                bfr[nt][0] = __float_as_uint(bp[0]);
                bfr[nt][1] = __float_as_uint(bp[4]);
            }
            #pragma unroll
            for (int nt = 0; nt < 8; nt++)
                mma_tf32(Sacc[nt], afr, bfr[nt]);
        }
        __syncthreads();   // done reading K

        // V tile -> KVs (rows n, cols d)
        #pragma unroll
        for (int i = 0; i < 16; i++) {
            int f = i * 128 + tid;
            int r = f >> 5, c4 = f & 31;
            int n = n0 + r;
            const float* src = base + (size_t)(n >> 3) * N3C + 2 * NC + ((n & 7) << 7) + (c4 << 2);
            *(float4*)&KVs[r * ATS + (c4 << 2)] = *(const float4*)src;
        }

        // P = 2^S (no max: |S| << fp32 exp range by construction); row sums
        #pragma unroll
        for (int h = 0; h < 2; h++) {
            float ls = 0.f;
            int prow = (warpM + g + 8 * h) * PST + 2 * q;
            #pragma unroll
            for (int nt = 0; nt < 8; nt++) {
                float e0 = ex2(Sacc[nt][2 * h + 0]);
                float e1 = ex2(Sacc[nt][2 * h + 1]);
                ls += e0 + e1;
                float2 p2; p2.x = e0; p2.y = e1;
                *(float2*)&Ps[prow + nt * 8] = p2;
            }
            ls += __shfl_xor_sync(0xffffffffu, ls, 1);
            ls += __shfl_xor_sync(0xffffffffu, ls, 2);
            lsum[h] += ls;
        }
        __syncthreads();   // V + P visible

        // O += P @ V : 8 ksteps over n=64, 16 n-tiles over d=128
        #pragma unroll
        for (int ks = 0; ks < 8; ks++) {
            int k0 = ks * 8;
            uint32_t afr[4];
            const float* ap = Ps + (warpM + g) * PST + k0 + q;
            afr[0] = __float_as_uint(ap[0]);
            afr[1] = __float_as_uint(ap[8 * PST]);
            afr[2] = __float_as_uint(ap[4]);
            afr[3] = __float_as_uint(ap[8 * PST + 4]);
            const float* v0 = KVs + (k0 + q) * ATS;
            const float* v4 = KVs + (k0 + q + 4) * ATS;
            #pragma unroll
            for (int nt = 0; nt < 16; nt++) {
                uint32_t bfr[2];
                bfr[0] = __float_as_uint(v0[nt * 8 + g]);
                bfr[1] = __float_as_uint(v4[nt * 8 + g]);
                mma_tf32(Oacc[nt], afr, bfr);
            }
        }
    }

    // Epilogue: out = O / lsum  (flat layout == raw reshape back)
    #pragma unroll
    for (int h = 0; h < 2; h++) {
        float inv = 1.0f / lsum[h];
        int row = m0 + warpM + g + 8 * h;
        float* dst = outp + (size_t)bh * (NL * NCH) + (size_t)row * NCH + 2 * q;
        #pragma unroll
        for (int nt = 0; nt < 16; nt++) {
            float2 w;
            w.x = Oacc[nt][2 * h + 0] * inv;
            w.y = Oacc[nt][2 * h + 1] * inv;
            *(float2*)&dst[nt * 8] = w;
        }
    }
}

// ---------------------------------------------------------------------------
extern "C" void kernel_launch(void* const* d_in, const int* in_sizes, int n_in,
                              void* d_out, int out_size)
{
    const float* x     = (const float*)d_in[0];
    const float* ln_g  = (const float*)d_in[1];
    const float* ln_b  = (const float*)d_in[2];
    const float* w_qkv = (const float*)d_in[3];
    const float* b_qkv = (const float*)d_in[4];
    const float* w_out = (const float*)d_in[5];
    const float* b_out = (const float*)d_in[6];
    float* out = (float*)d_out;

    float *xn, *qkvb, *attnb, *wqkvT, *woutT;
    cudaGetSymbolAddress((void**)&xn,    g_xn);
    cudaGetSymbolAddress((void**)&qkvb,  g_qkv);
    cudaGetSymbolAddress((void**)&attnb, g_attn);
    cudaGetSymbolAddress((void**)&wqkvT, g_wqkvT);
    cudaGetSymbolAddress((void**)&woutT, g_woutT);

    cudaFuncSetAttribute(gemm_mma_kernel<0>,
                         cudaFuncAttributeMaxDynamicSharedMemorySize, SMEM_GEMM);
    cudaFuncSetAttribute(gemm_mma_kernel<1>,
                         cudaFuncAttributeMaxDynamicSharedMemorySize, SMEM_GEMM);
    cudaFuncSetAttribute(attn_kernel,
                         cudaFuncAttributeMaxDynamicSharedMemorySize, ATT_SMEM);

    // 0) Transpose weights to [N, K]
    transpose_kernel<<<dim3(N3C / 32, NC / 32), dim3(32, 8)>>>(w_qkv, wqkvT, NC, N3C);
    transpose_kernel<<<dim3(NC / 32,  NC / 32), dim3(32, 8)>>>(w_out, woutT, NC, NC);

    // 1) LayerNorm
    ln_kernel<<<NB * NL, 256>>>(x, ln_g, ln_b, xn);

    // 2) QKV projection (tf32 mma; q cols also pre-scaled by log2e)
    gemm_mma_kernel<0><<<dim3(N3C / BN, (NB * NL) / BM), 256, SMEM_GEMM>>>(
        xn, wqkvT, b_qkv, nullptr, qkvb, N3C);

    // 3) Attention (tf32 mma, log2-domain no-max softmax)
    attn_kernel<<<dim3(NL / BMA, NBH), 128, ATT_SMEM>>>(qkvb, attnb);

    // 4) Output projection + bias + residual(xn)
    gemm_mma_kernel<1><<<dim3(NC / BN, (NB * NL) / BM), 256, SMEM_GEMM>>>(
        attnb, woutT, b_out, xn, out, NC);
}

// round 9
// speedup vs baseline: 6.7307x; 2.0995x over previous
#include <cuda_runtime.h>
#include <cuda_bf16.h>
#include <cstdint>
#include <math.h>

// Problem dims
#define NB   8
#define NL   1024
#define NC   1024
#define NH   8
#define NCH  128
#define NBH  64
#define N3C  3072
#define QK_SCALE 0.29730177875068026f  // 128^(-1/4)
#define LOG2E    1.4426950408889634f

// Scratch (allocation-free rule: __device__ globals)
__device__ float          g_xn   [(size_t)NB * NL * NC];    // fp32 (residual)
__device__ __nv_bfloat16  g_xnh  [(size_t)NB * NL * NC];    // bf16 (GEMM A)
__device__ __nv_bfloat16  g_qkv  [(size_t)NB * NL * N3C];
__device__ __nv_bfloat16  g_attn [(size_t)NB * NL * NC];
__device__ __nv_bfloat16  g_wqkvT[(size_t)N3C * NC];
__device__ __nv_bfloat16  g_woutT[(size_t)NC * NC];

// ---------------------------------------------------------------------------
// Helpers (sm_80+ PTX only; target is plain compute_103 — no 'a' features)
// ---------------------------------------------------------------------------
__device__ __forceinline__ uint32_t smem_u32(const void* p) {
    uint32_t a;
    asm("{ .reg .u64 t; cvta.to.shared.u64 t, %1; cvt.u32.u64 %0, t; }" : "=r"(a) : "l"(p));
    return a;
}
__device__ __forceinline__ void cp16(uint32_t dst, const void* src) {
    asm volatile("cp.async.cg.shared.global [%0], [%1], 16;" :: "r"(dst), "l"(src));
}
#define CP_COMMIT() asm volatile("cp.async.commit_group;" ::: "memory")
#define CP_WAIT(n)  asm volatile("cp.async.wait_group %0;" :: "n"(n) : "memory")

__device__ __forceinline__ void mma_bf16(float* d, const uint32_t* a, const uint32_t* b) {
    asm volatile("mma.sync.aligned.m16n8k16.row.col.f32.bf16.bf16.f32 "
        "{%0,%1,%2,%3}, {%4,%5,%6,%7}, {%8,%9}, {%0,%1,%2,%3};"
        : "+f"(d[0]), "+f"(d[1]), "+f"(d[2]), "+f"(d[3])
        : "r"(a[0]), "r"(a[1]), "r"(a[2]), "r"(a[3]), "r"(b[0]), "r"(b[1]));
}
#define LDSM_X4(r, addr) \
    asm volatile("ldmatrix.sync.aligned.m8n8.x4.shared.b16 {%0,%1,%2,%3}, [%4];" \
        : "=r"((r)[0]), "=r"((r)[1]), "=r"((r)[2]), "=r"((r)[3]) : "r"(addr))
#define LDSM_X4_T(r, addr) \
    asm volatile("ldmatrix.sync.aligned.m8n8.x4.trans.shared.b16 {%0,%1,%2,%3}, [%4];" \
        : "=r"((r)[0]), "=r"((r)[1]), "=r"((r)[2]), "=r"((r)[3]) : "r"(addr))

__device__ __forceinline__ float ex2(float x) {
    float r;
    asm("ex2.approx.f32 %0, %1;" : "=f"(r) : "f"(x));
    return r;
}

// ---------------------------------------------------------------------------
// LayerNorm: fp32 out (residual) + bf16 out (GEMM operand)
// ---------------------------------------------------------------------------
__global__ void __launch_bounds__(256) ln_kernel(
    const float* __restrict__ x, const float* __restrict__ gamma,
    const float* __restrict__ beta, float* __restrict__ xn,
    __nv_bfloat16* __restrict__ xnh)
{
    int row = blockIdx.x;
    int t   = threadIdx.x;
    const float4* xr = reinterpret_cast<const float4*>(x + (size_t)row * NC);
    float4 v = xr[t];
    float s  = v.x + v.y + v.z + v.w;
    float ss = v.x*v.x + v.y*v.y + v.z*v.z + v.w*v.w;
    #pragma unroll
    for (int o = 16; o; o >>= 1) {
        s  += __shfl_xor_sync(0xffffffffu, s,  o);
        ss += __shfl_xor_sync(0xffffffffu, ss, o);
    }
    __shared__ float rs[8], rss[8], stat[2];
    int warp = t >> 5, lane = t & 31;
    if (lane == 0) { rs[warp] = s; rss[warp] = ss; }
    __syncthreads();
    if (t == 0) {
        float a = 0.f, b2 = 0.f;
        #pragma unroll
        for (int i = 0; i < 8; i++) { a += rs[i]; b2 += rss[i]; }
        float mu  = a * (1.0f / NC);
        float var = b2 * (1.0f / NC) - mu * mu;
        stat[0] = mu;
        stat[1] = rsqrtf(var + 1e-5f);
    }
    __syncthreads();
    float mu = stat[0], rstd = stat[1];
    float4 g4 = reinterpret_cast<const float4*>(gamma)[t];
    float4 b4 = reinterpret_cast<const float4*>(beta )[t];
    float4 o;
    o.x = (v.x - mu) * rstd * g4.x + b4.x;
    o.y = (v.y - mu) * rstd * g4.y + b4.y;
    o.z = (v.z - mu) * rstd * g4.z + b4.z;
    o.w = (v.w - mu) * rstd * g4.w + b4.w;
    reinterpret_cast<float4*>(xn + (size_t)row * NC)[t] = o;
    __nv_bfloat162 h0 = __float22bfloat162_rn(make_float2(o.x, o.y));
    __nv_bfloat162 h1 = __float22bfloat162_rn(make_float2(o.z, o.w));
    uint2 u; u.x = *(uint32_t*)&h0; u.y = *(uint32_t*)&h1;
    *reinterpret_cast<uint2*>(xnh + (size_t)row * NC + t * 4) = u;
}

// ---------------------------------------------------------------------------
// 32x32 tiled transpose, fp32 -> bf16
// ---------------------------------------------------------------------------
__global__ void __launch_bounds__(256) transpose_kernel(
    const float* __restrict__ src, __nv_bfloat16* __restrict__ dst, int R, int Ccols)
{
    __shared__ float t[32][33];
    int bx = blockIdx.x * 32, by = blockIdx.y * 32;
    #pragma unroll
    for (int i = 0; i < 4; i++)
        t[threadIdx.y + i * 8][threadIdx.x] =
            src[(size_t)(by + threadIdx.y + i * 8) * Ccols + bx + threadIdx.x];
    __syncthreads();
    #pragma unroll
    for (int i = 0; i < 4; i++)
        dst[(size_t)(bx + threadIdx.y + i * 8) * R + by + threadIdx.x] =
            __float2bfloat16(t[threadIdx.x][threadIdx.y + i * 8]);
}

// ---------------------------------------------------------------------------
// bf16 mma.sync GEMM: C[M,N] = A[M,K] @ BT[N,K]^T (+bias; MODE epilogue)
// CTA 128x128, BK=64, 8 warps (2x4), warp 64x32, ldmatrix frags, 3-stage cp.async.
// MODE 0: bf16 out, q cols *= QK_SCALE*LOG2E, k cols *= QK_SCALE.
// MODE 1: fp32 out, += bias + resid.
// ---------------------------------------------------------------------------
#define BM 128
#define BN 128
#define BK 64
#define KTOT 1024
#define NCHUNK (KTOT / BK)          // 16
#define GST 72                      // smem halves stride (64 + 8) -> odd 16B quads
#define STAGE_H (2 * BM * GST)      // halves per stage (A + B)
#define SMEM_GEMM (3 * STAGE_H * 2) // 110592 bytes

template <int MODE>
__global__ void __launch_bounds__(256, 2) gemm_bf16_kernel(
    const __nv_bfloat16* __restrict__ A, const __nv_bfloat16* __restrict__ BT,
    const float* __restrict__ bias, const float* __restrict__ resid,
    void* __restrict__ Cm, int N)
{
    extern __shared__ __align__(16) __nv_bfloat16 smh[];
    uint32_t sbase = smem_u32(smh);
    int tid = threadIdx.x;
    int wid = tid >> 5, lane = tid & 31;
    int g = lane >> 2, q = lane & 3;
    const int bm = blockIdx.y * BM;
    const int bn = blockIdx.x * BN;
    const int warpM = (wid >> 2) * 64;
    const int warpN = (wid & 3) * 32;

    // ldmatrix lane address components
    int a_r = (lane & 7) | (((lane >> 3) & 1) << 3);   // A/P row within 16
    int a_c = (lane >> 4) << 3;                        // A/P k-halves offset
    int b_r = (lane & 7) | (((lane >> 4) & 1) << 3);   // B row within 16
    int b_c = ((lane >> 3) & 1) << 3;                  // B k-halves offset

    auto load_chunk = [&](int kk, int stg) {
        uint32_t sA = sbase + (uint32_t)(stg * STAGE_H) * 2;
        uint32_t sB = sA + (uint32_t)(BM * GST) * 2;
        #pragma unroll
        for (int i = 0; i < 4; i++) {     // A: 128 rows x 8 chunks(8h)
            int f = i * 256 + tid;
            int r = f >> 3, c = f & 7;
            cp16(sA + (uint32_t)(r * GST + c * 8) * 2,
                 A + (size_t)(bm + r) * KTOT + kk + c * 8);
        }
        #pragma unroll
        for (int i = 0; i < 4; i++) {
            int f = i * 256 + tid;
            int r = f >> 3, c = f & 7;
            cp16(sB + (uint32_t)(r * GST + c * 8) * 2,
                 BT + (size_t)(bn + r) * KTOT + kk + c * 8);
        }
        CP_COMMIT();
    };

    float accf[4][4][4];
    #pragma unroll
    for (int mt = 0; mt < 4; mt++)
        #pragma unroll
        for (int nt = 0; nt < 4; nt++)
            #pragma unroll
            for (int r = 0; r < 4; r++) accf[mt][nt][r] = 0.f;

    load_chunk(0, 0);
    load_chunk(BK, 1);

    for (int c = 0; c < NCHUNK; c++) {
        if (c < NCHUNK - 1) CP_WAIT(1); else CP_WAIT(0);
        __syncthreads();
        if (c + 2 < NCHUNK) load_chunk((c + 2) * BK, (c + 2) % 3);
        uint32_t sA = sbase + (uint32_t)((c % 3) * STAGE_H) * 2;
        uint32_t sB = sA + (uint32_t)(BM * GST) * 2;
        #pragma unroll
        for (int ks = 0; ks < 4; ks++) {
            int k0 = ks * 16;
            uint32_t afr[4][4], bfr[2][4];
            #pragma unroll
            for (int mt = 0; mt < 4; mt++)
                LDSM_X4(afr[mt], sA + (uint32_t)((warpM + mt * 16 + a_r) * GST + k0 + a_c) * 2);
            #pragma unroll
            for (int np = 0; np < 2; np++)
                LDSM_X4(bfr[np], sB + (uint32_t)((warpN + np * 16 + b_r) * GST + k0 + b_c) * 2);
            #pragma unroll
            for (int mt = 0; mt < 4; mt++)
                #pragma unroll
                for (int np = 0; np < 2; np++) {
                    mma_bf16(accf[mt][np * 2 + 0], afr[mt], &bfr[np][0]);
                    mma_bf16(accf[mt][np * 2 + 1], afr[mt], &bfr[np][2]);
                }
        }
        __syncthreads();
    }

    #pragma unroll
    for (int mt = 0; mt < 4; mt++) {
        int row0 = bm + warpM + mt * 16 + g;
        #pragma unroll
        for (int nt = 0; nt < 4; nt++) {
            int col = bn + warpN + nt * 8 + q * 2;
            float2 bb = *(const float2*)&bias[col];
            float mscale = 1.0f;
            if (MODE == 0)
                mscale = (col < NC) ? (QK_SCALE * LOG2E)
                                    : ((col < 2 * NC) ? QK_SCALE : 1.0f);
            #pragma unroll
            for (int h = 0; h < 2; h++) {
                int row = row0 + h * 8;
                float2 o;
                o.x = accf[mt][nt][h * 2 + 0] + bb.x;
                o.y = accf[mt][nt][h * 2 + 1] + bb.y;
                if (MODE == 0) {
                    o.x *= mscale; o.y *= mscale;
                    __nv_bfloat162 hb = __float22bfloat162_rn(o);
                    *reinterpret_cast<__nv_bfloat162*>(
                        (__nv_bfloat16*)Cm + (size_t)row * N + col) = hb;
                } else {
                    float2 rr = *(const float2*)&resid[(size_t)row * NC + col];
                    o.x += rr.x; o.y += rr.y;
                    *reinterpret_cast<float2*>((float*)Cm + (size_t)row * N + col) = o;
                }
            }
        }
    }
}

// ---------------------------------------------------------------------------
// bf16 mma.sync flash attention, RAW-RESHAPED layout, no-max log2 softmax.
// BMA=64 q, BNA=64 kv, d=128. 128 threads = 4 warps x 16 m-rows.
// ldmatrix for Q/K/P frags, ldmatrix.trans for V.
// ---------------------------------------------------------------------------
#define BMA 64
#define BNA 64
#define ATSH 136            // Q/KV smem halves stride (128+8)
#define PSTH 72             // P smem halves stride (64+8)
#define QOFFH  0
#define KVOFFH (BMA * ATSH)
#define PSOFFH (KVOFFH + BNA * ATSH)
#define ATT_SMEM ((PSOFFH + BMA * PSTH) * 2)   // 44032 B

__global__ void __launch_bounds__(128, 3) attn_kernel(
    const __nv_bfloat16* __restrict__ qkv, __nv_bfloat16* __restrict__ outp)
{
    extern __shared__ __align__(16) __nv_bfloat16 smh[];
    __nv_bfloat16* Qs = smh + QOFFH;
    __nv_bfloat16* KVs = smh + KVOFFH;
    __nv_bfloat16* Ps = smh + PSOFFH;
    uint32_t uQ = smem_u32(Qs), uKV = smem_u32(KVs), uP = smem_u32(Ps);

    int tid = threadIdx.x;
    int wid = tid >> 5, lane = tid & 31;
    int g = lane >> 2, q = lane & 3;
    int bh  = blockIdx.y;
    int m0  = blockIdx.x * BMA;
    int bb  = bh >> 3, hh = bh & 7;
    const __nv_bfloat16* base = qkv + (size_t)(bb * 1024 + hh * 128) * N3C;
    const int warpM = wid * 16;

    int a_r = (lane & 7) | (((lane >> 3) & 1) << 3);
    int a_c = (lane >> 4) << 3;
    int b_r = (lane & 7) | (((lane >> 4) & 1) << 3);
    int b_c = ((lane >> 3) & 1) << 3;
    int v_r = (lane & 7) | (((lane >> 3) & 1) << 3);   // k(n) row select
    int v_c = (lane >> 4) << 3;                        // d +8 select

    // Load Q tile: 64 rows x 16 chunks of 8 halves (raw-reshape gather)
    #pragma unroll
    for (int i = 0; i < 8; i++) {
        int f = i * 128 + tid;
        int r = f >> 4, c8 = f & 15;
        int l2 = m0 + r;
        const __nv_bfloat16* src = base + (size_t)(l2 >> 3) * N3C + ((l2 & 7) << 7) + c8 * 8;
        *(uint4*)&Qs[r * ATSH + c8 * 8] = *(const uint4*)src;
    }

    float Oacc[16][4];
    float lsum[2] = {0.f, 0.f};
    #pragma unroll
    for (int nt = 0; nt < 16; nt++)
        #pragma unroll
        for (int r = 0; r < 4; r++) Oacc[nt][r] = 0.f;

    for (int kt = 0; kt < NL / BNA; kt++) {
        int n0 = kt * BNA;
        __syncthreads();   // prev PV done with KVs/Ps; Q visible (1st iter)

        // K tile -> KVs
        #pragma unroll
        for (int i = 0; i < 8; i++) {
            int f = i * 128 + tid;
            int r = f >> 4, c8 = f & 15;
            int n = n0 + r;
            const __nv_bfloat16* src = base + (size_t)(n >> 3) * N3C + NC + ((n & 7) << 7) + c8 * 8;
            *(uint4*)&KVs[r * ATSH + c8 * 8] = *(const uint4*)src;
        }
        __syncthreads();

        // S = Q K^T : 8 ksteps of k16 over d=128
        float Sacc[8][4];
        #pragma unroll
        for (int nt = 0; nt < 8; nt++)
            #pragma unroll
            for (int r = 0; r < 4; r++) Sacc[nt][r] = 0.f;
        #pragma unroll
        for (int ks = 0; ks < 8; ks++) {
            int k0 = ks * 16;
            uint32_t afr[4], bfr[4][4];
            LDSM_X4(afr, uQ + (uint32_t)((warpM + a_r) * ATSH + k0 + a_c) * 2);
            #pragma unroll
            for (int np = 0; np < 4; np++)
                LDSM_X4(bfr[np], uKV + (uint32_t)((np * 16 + b_r) * ATSH + k0 + b_c) * 2);
            #pragma unroll
            for (int np = 0; np < 4; np++) {
                mma_bf16(Sacc[np * 2 + 0], afr, &bfr[np][0]);
                mma_bf16(Sacc[np * 2 + 1], afr, &bfr[np][2]);
            }
        }
        __syncthreads();   // done reading K

        // V tile -> KVs
        #pragma unroll
        for (int i = 0; i < 8; i++) {
            int f = i * 128 + tid;
            int r = f >> 4, c8 = f & 15;
            int n = n0 + r;
            const __nv_bfloat16* src = base + (size_t)(n >> 3) * N3C + 2 * NC + ((n & 7) << 7) + c8 * 8;
            *(uint4*)&KVs[r * ATSH + c8 * 8] = *(const uint4*)src;
        }

        // P = 2^S (log2-domain, no max), bf16 store, fp32 row sums
        #pragma unroll
        for (int h = 0; h < 2; h++) {
            float ls = 0.f;
            int prow = (warpM + g + 8 * h) * PSTH + 2 * q;
            #pragma unroll
            for (int nt = 0; nt < 8; nt++) {
                float e0 = ex2(Sacc[nt][2 * h + 0]);
                float e1 = ex2(Sacc[nt][2 * h + 1]);
                ls += e0 + e1;
                *reinterpret_cast<__nv_bfloat162*>(&Ps[prow + nt * 8]) =
                    __float22bfloat162_rn(make_float2(e0, e1));
            }
            ls += __shfl_xor_sync(0xffffffffu, ls, 1);
            ls += __shfl_xor_sync(0xffffffffu, ls, 2);
            lsum[h] += ls;
        }
        __syncthreads();   // V + P visible

        // O += P @ V : 4 ksteps of k16 over n=64; V via ldmatrix.trans
        #pragma unroll
        for (int kv = 0; kv < 4; kv++) {
            int k0 = kv * 16;
            uint32_t afr[4];
            LDSM_X4(afr, uP + (uint32_t)((warpM + a_r) * PSTH + k0 + a_c) * 2);
            #pragma unroll
            for (int dp = 0; dp < 8; dp++) {
                uint32_t vfr[4];
                LDSM_X4_T(vfr, uKV + (uint32_t)((k0 + v_r) * ATSH + dp * 16 + v_c) * 2);
                mma_bf16(Oacc[dp * 2 + 0], afr, &vfr[0]);
                mma_bf16(Oacc[dp * 2 + 1], afr, &vfr[2]);
            }
        }
    }

    // Epilogue: out = O / lsum, bf16 (flat layout == raw reshape back)
    #pragma unroll
    for (int h = 0; h < 2; h++) {
        float inv = 1.0f / lsum[h];
        int row = m0 + warpM + g + 8 * h;
        __nv_bfloat16* dst = outp + (size_t)bh * (NL * NCH) + (size_t)row * NCH + 2 * q;
        #pragma unroll
        for (int nt = 0; nt < 16; nt++) {
            float2 w;
            w.x = Oacc[nt][2 * h + 0] * inv;
            w.y = Oacc[nt][2 * h + 1] * inv;
            *reinterpret_cast<__nv_bfloat162*>(&dst[nt * 8]) = __float22bfloat162_rn(w);
        }
    }
}

// ---------------------------------------------------------------------------
extern "C" void kernel_launch(void* const* d_in, const int* in_sizes, int n_in,
                              void* d_out, int out_size)
{
    const float* x     = (const float*)d_in[0];
    const float* ln_g  = (const float*)d_in[1];
    const float* ln_b  = (const float*)d_in[2];
    const float* w_qkv = (const float*)d_in[3];
    const float* b_qkv = (const float*)d_in[4];
    const float* w_out = (const float*)d_in[5];
    const float* b_out = (const float*)d_in[6];
    float* out = (float*)d_out;

    float *xn;
    __nv_bfloat16 *xnh, *qkvb, *attnb, *wqkvT, *woutT;
    cudaGetSymbolAddress((void**)&xn,    g_xn);
    cudaGetSymbolAddress((void**)&xnh,   g_xnh);
    cudaGetSymbolAddress((void**)&qkvb,  g_qkv);
    cudaGetSymbolAddress((void**)&attnb, g_attn);
    cudaGetSymbolAddress((void**)&wqkvT, g_wqkvT);
    cudaGetSymbolAddress((void**)&woutT, g_woutT);

    cudaFuncSetAttribute(gemm_bf16_kernel<0>,
                         cudaFuncAttributeMaxDynamicSharedMemorySize, SMEM_GEMM);
    cudaFuncSetAttribute(gemm_bf16_kernel<1>,
                         cudaFuncAttributeMaxDynamicSharedMemorySize, SMEM_GEMM);
    cudaFuncSetAttribute(attn_kernel,
                         cudaFuncAttributeMaxDynamicSharedMemorySize, ATT_SMEM);

    // 0) Transpose weights to [N, K] bf16
    transpose_kernel<<<dim3(N3C / 32, NC / 32), dim3(32, 8)>>>(w_qkv, wqkvT, NC, N3C);
    transpose_kernel<<<dim3(NC / 32,  NC / 32), dim3(32, 8)>>>(w_out, woutT, NC, NC);

    // 1) LayerNorm (fp32 + bf16 outputs)
    ln_kernel<<<NB * NL, 256>>>(x, ln_g, ln_b, xn, xnh);

    // 2) QKV projection (bf16 mma; q cols pre-scaled by log2e) -> bf16
    gemm_bf16_kernel<0><<<dim3(N3C / BN, (NB * NL) / BM), 256, SMEM_GEMM>>>(
        xnh, wqkvT, b_qkv, nullptr, qkvb, N3C);

    // 3) Attention (bf16 mma, log2-domain no-max softmax) -> bf16
    attn_kernel<<<dim3(NL / BMA, NBH), 128, ATT_SMEM>>>(qkvb, attnb);

    // 4) Output projection + bias + residual(fp32 xn) -> fp32
    gemm_bf16_kernel<1><<<dim3(NC / BN, (NB * NL) / BM), 256, SMEM_GEMM>>>(
        attnb, woutT, b_out, xn, out, NC);
}

// round 10
// speedup vs baseline: 6.7346x; 1.0006x over previous
#include <cuda_runtime.h>
#include <cuda_bf16.h>
#include <cstdint>
#include <math.h>

// Problem dims
#define NB   8
#define NL   1024
#define NC   1024
#define NH   8
#define NCH  128
#define NBH  64
#define N3C  3072
#define QK_SCALE 0.29730177875068026f  // 128^(-1/4)
#define LOG2E    1.4426950408889634f

// Scratch (allocation-free rule: __device__ globals)
__device__ float          g_xn   [(size_t)NB * NL * NC];    // fp32 (residual)
__device__ __nv_bfloat16  g_xnh  [(size_t)NB * NL * NC];    // bf16 (GEMM A)
__device__ __nv_bfloat16  g_qkv  [(size_t)NB * NL * N3C];
__device__ __nv_bfloat16  g_attn [(size_t)NB * NL * NC];
__device__ __nv_bfloat16  g_wqkvh[(size_t)NC * N3C];        // bf16, native [K,N]
__device__ __nv_bfloat16  g_wouth[(size_t)NC * NC];         // bf16, native [K,N]

// ---------------------------------------------------------------------------
// Helpers (sm_80+ PTX only; target is plain compute_103 — no 'a' features)
// ---------------------------------------------------------------------------
__device__ __forceinline__ uint32_t smem_u32(const void* p) {
    uint32_t a;
    asm("{ .reg .u64 t; cvta.to.shared.u64 t, %1; cvt.u32.u64 %0, t; }" : "=r"(a) : "l"(p));
    return a;
}
__device__ __forceinline__ void cp16(uint32_t dst, const void* src) {
    asm volatile("cp.async.cg.shared.global [%0], [%1], 16;" :: "r"(dst), "l"(src));
}
#define CP_COMMIT() asm volatile("cp.async.commit_group;" ::: "memory")
#define CP_WAIT(n)  asm volatile("cp.async.wait_group %0;" :: "n"(n) : "memory")

__device__ __forceinline__ void mma_bf16(float* d, const uint32_t* a, const uint32_t* b) {
    asm volatile("mma.sync.aligned.m16n8k16.row.col.f32.bf16.bf16.f32 "
        "{%0,%1,%2,%3}, {%4,%5,%6,%7}, {%8,%9}, {%0,%1,%2,%3};"
        : "+f"(d[0]), "+f"(d[1]), "+f"(d[2]), "+f"(d[3])
        : "r"(a[0]), "r"(a[1]), "r"(a[2]), "r"(a[3]), "r"(b[0]), "r"(b[1]));
}
#define LDSM_X4(r, addr) \
    asm volatile("ldmatrix.sync.aligned.m8n8.x4.shared.b16 {%0,%1,%2,%3}, [%4];" \
        : "=r"((r)[0]), "=r"((r)[1]), "=r"((r)[2]), "=r"((r)[3]) : "r"(addr))
#define LDSM_X4_T(r, addr) \
    asm volatile("ldmatrix.sync.aligned.m8n8.x4.trans.shared.b16 {%0,%1,%2,%3}, [%4];" \
        : "=r"((r)[0]), "=r"((r)[1]), "=r"((r)[2]), "=r"((r)[3]) : "r"(addr))

__device__ __forceinline__ float ex2(float x) {
    float r;
    asm("ex2.approx.f32 %0, %1;" : "=f"(r) : "f"(x));
    return r;
}

// ---------------------------------------------------------------------------
// LayerNorm: fp32 out (residual) + bf16 out (GEMM operand)
// ---------------------------------------------------------------------------
__global__ void __launch_bounds__(256) ln_kernel(
    const float* __restrict__ x, const float* __restrict__ gamma,
    const float* __restrict__ beta, float* __restrict__ xn,
    __nv_bfloat16* __restrict__ xnh)
{
    int row = blockIdx.x;
    int t   = threadIdx.x;
    const float4* xr = reinterpret_cast<const float4*>(x + (size_t)row * NC);
    float4 v = xr[t];
    float s  = v.x + v.y + v.z + v.w;
    float ss = v.x*v.x + v.y*v.y + v.z*v.z + v.w*v.w;
    #pragma unroll
    for (int o = 16; o; o >>= 1) {
        s  += __shfl_xor_sync(0xffffffffu, s,  o);
        ss += __shfl_xor_sync(0xffffffffu, ss, o);
    }
    __shared__ float rs[8], rss[8], stat[2];
    int warp = t >> 5, lane = t & 31;
    if (lane == 0) { rs[warp] = s; rss[warp] = ss; }
    __syncthreads();
    if (t == 0) {
        float a = 0.f, b2 = 0.f;
        #pragma unroll
        for (int i = 0; i < 8; i++) { a += rs[i]; b2 += rss[i]; }
        float mu  = a * (1.0f / NC);
        float var = b2 * (1.0f / NC) - mu * mu;
        stat[0] = mu;
        stat[1] = rsqrtf(var + 1e-5f);
    }
    __syncthreads();
    float mu = stat[0], rstd = stat[1];
    float4 g4 = reinterpret_cast<const float4*>(gamma)[t];
    float4 b4 = reinterpret_cast<const float4*>(beta )[t];
    float4 o;
    o.x = (v.x - mu) * rstd * g4.x + b4.x;
    o.y = (v.y - mu) * rstd * g4.y + b4.y;
    o.z = (v.z - mu) * rstd * g4.z + b4.z;
    o.w = (v.w - mu) * rstd * g4.w + b4.w;
    reinterpret_cast<float4*>(xn + (size_t)row * NC)[t] = o;
    __nv_bfloat162 h0 = __float22bfloat162_rn(make_float2(o.x, o.y));
    __nv_bfloat162 h1 = __float22bfloat162_rn(make_float2(o.z, o.w));
    uint2 u; u.x = *(uint32_t*)&h0; u.y = *(uint32_t*)&h1;
    *reinterpret_cast<uint2*>(xnh + (size_t)row * NC + t * 4) = u;
}

// ---------------------------------------------------------------------------
// Elementwise fp32 -> bf16 convert (weights; layout preserved)
// ---------------------------------------------------------------------------
__global__ void __launch_bounds__(256) cvt_kernel(
    const float* __restrict__ src, __nv_bfloat16* __restrict__ dst)
{
    size_t i = ((size_t)blockIdx.x * 256 + threadIdx.x) * 8;
    float4 a = *(const float4*)(src + i);
    float4 b = *(const float4*)(src + i + 4);
    __nv_bfloat162 h0 = __float22bfloat162_rn(make_float2(a.x, a.y));
    __nv_bfloat162 h1 = __float22bfloat162_rn(make_float2(a.z, a.w));
    __nv_bfloat162 h2 = __float22bfloat162_rn(make_float2(b.x, b.y));
    __nv_bfloat162 h3 = __float22bfloat162_rn(make_float2(b.z, b.w));
    uint4 u;
    u.x = *(uint32_t*)&h0; u.y = *(uint32_t*)&h1;
    u.z = *(uint32_t*)&h2; u.w = *(uint32_t*)&h3;
    *reinterpret_cast<uint4*>(dst + i) = u;
}

// ---------------------------------------------------------------------------
// bf16 mma.sync GEMM: C[M,N] = A[M,K] @ B[K,N] (+bias; MODE epilogue)
// B in NATIVE [K,N] layout; B fragments via ldmatrix.trans (no pre-transpose).
// CTA 128x128, BK=64, 8 warps (2x4), warp 64x32, 3-stage cp.async,
// ONE __syncthreads per chunk.
// MODE 0: bf16 out, q cols *= QK_SCALE*LOG2E, k cols *= QK_SCALE.
// MODE 1: fp32 out, += bias + resid.
// ---------------------------------------------------------------------------
#define BM 128
#define BN 128
#define BK 64
#define KTOT 1024
#define NCHUNK (KTOT / BK)              // 16
#define GST 72                          // A smem halves stride (64+8)
#define BNS 136                         // B smem halves stride (128+8)
#define STAGE_H (BM * GST + BK * BNS)   // 17920 halves
#define SMEM_GEMM (3 * STAGE_H * 2)     // 107520 bytes

template <int MODE>
__global__ void __launch_bounds__(256, 2) gemm_bf16_kernel(
    const __nv_bfloat16* __restrict__ A, const __nv_bfloat16* __restrict__ Bw,
    const float* __restrict__ bias, const float* __restrict__ resid,
    void* __restrict__ Cm, int N)
{
    extern __shared__ __align__(16) __nv_bfloat16 smh[];
    uint32_t sbase = smem_u32(smh);
    int tid = threadIdx.x;
    int wid = tid >> 5, lane = tid & 31;
    int g = lane >> 2, q = lane & 3;
    const int bm = blockIdx.y * BM;
    const int bn = blockIdx.x * BN;
    const int warpM = (wid >> 2) * 64;
    const int warpN = (wid & 3) * 32;

    // ldmatrix lane address components
    int a_r = (lane & 7) | (((lane >> 3) & 1) << 3);   // A row within 16
    int a_c = (lane >> 4) << 3;                        // A k-halves offset
    int v_r = (lane & 7) | (((lane >> 3) & 1) << 3);   // B(k) row select
    int v_c = (lane >> 4) << 3;                        // B(n) +8 select

    auto load_chunk = [&](int kk, int stg) {
        uint32_t sA = sbase + (uint32_t)(stg * STAGE_H) * 2;
        uint32_t sB = sA + (uint32_t)(BM * GST) * 2;
        #pragma unroll
        for (int i = 0; i < 4; i++) {     // A: 128 rows x 8 chunks(8h)
            int f = i * 256 + tid;
            int r = f >> 3, c = f & 7;
            cp16(sA + (uint32_t)(r * GST + c * 8) * 2,
                 A + (size_t)(bm + r) * KTOT + kk + c * 8);
        }
        #pragma unroll
        for (int i = 0; i < 4; i++) {     // B: 64 k-rows x 16 chunks(8h)
            int f = i * 256 + tid;
            int r = f >> 4, c = f & 15;
            cp16(sB + (uint32_t)(r * BNS + c * 8) * 2,
                 Bw + (size_t)(kk + r) * N + bn + c * 8);
        }
        CP_COMMIT();
    };

    float accf[4][4][4];
    #pragma unroll
    for (int mt = 0; mt < 4; mt++)
        #pragma unroll
        for (int nt = 0; nt < 4; nt++)
            #pragma unroll
            for (int r = 0; r < 4; r++) accf[mt][nt][r] = 0.f;

    load_chunk(0, 0);
    load_chunk(BK, 1);

    for (int c = 0; c < NCHUNK; c++) {
        if (c < NCHUNK - 1) CP_WAIT(1); else CP_WAIT(0);
        __syncthreads();                    // single barrier per chunk
        if (c + 2 < NCHUNK) load_chunk((c + 2) * BK, (c + 2) % 3);
        uint32_t sA = sbase + (uint32_t)((c % 3) * STAGE_H) * 2;
        uint32_t sB = sA + (uint32_t)(BM * GST) * 2;
        #pragma unroll
        for (int ks = 0; ks < 4; ks++) {
            int k0 = ks * 16;
            uint32_t afr[4][4], bfr[2][4];
            #pragma unroll
            for (int mt = 0; mt < 4; mt++)
                LDSM_X4(afr[mt], sA + (uint32_t)((warpM + mt * 16 + a_r) * GST + k0 + a_c) * 2);
            #pragma unroll
            for (int np = 0; np < 2; np++)
                LDSM_X4_T(bfr[np], sB + (uint32_t)((k0 + v_r) * BNS + warpN + np * 16 + v_c) * 2);
            #pragma unroll
            for (int mt = 0; mt < 4; mt++)
                #pragma unroll
                for (int np = 0; np < 2; np++) {
                    mma_bf16(accf[mt][np * 2 + 0], afr[mt], &bfr[np][0]);
                    mma_bf16(accf[mt][np * 2 + 1], afr[mt], &bfr[np][2]);
                }
        }
    }

    #pragma unroll
    for (int mt = 0; mt < 4; mt++) {
        int row0 = bm + warpM + mt * 16 + g;
        #pragma unroll
        for (int nt = 0; nt < 4; nt++) {
            int col = bn + warpN + nt * 8 + q * 2;
            float2 bb = *(const float2*)&bias[col];
            float mscale = 1.0f;
            if (MODE == 0)
                mscale = (col < NC) ? (QK_SCALE * LOG2E)
                                    : ((col < 2 * NC) ? QK_SCALE : 1.0f);
            #pragma unroll
            for (int h = 0; h < 2; h++) {
                int row = row0 + h * 8;
                float2 o;
                o.x = accf[mt][nt][h * 2 + 0] + bb.x;
                o.y = accf[mt][nt][h * 2 + 1] + bb.y;
                if (MODE == 0) {
                    o.x *= mscale; o.y *= mscale;
                    __nv_bfloat162 hb = __float22bfloat162_rn(o);
                    *reinterpret_cast<__nv_bfloat162*>(
                        (__nv_bfloat16*)Cm + (size_t)row * N + col) = hb;
                } else {
                    float2 rr = *(const float2*)&resid[(size_t)row * NC + col];
                    o.x += rr.x; o.y += rr.y;
                    *reinterpret_cast<float2*>((float*)Cm + (size_t)row * N + col) = o;
                }
            }
        }
    }
}

// ---------------------------------------------------------------------------
// bf16 mma.sync flash attention, RAW-RESHAPED layout, no-max log2 softmax.
// BMA=128 q, BNA=64 kv, d=128. 256 threads = 8 warps x 16 m-rows.
// Halved KV gmem traffic and sync count vs BMA=64.
// ---------------------------------------------------------------------------
#define BMA 128
#define BNA 64
#define ATSH 136            // Q/KV smem halves stride (128+8)
#define PSTH 72             // P smem halves stride (64+8)
#define QOFFH  0
#define KVOFFH (BMA * ATSH)
#define PSOFFH (KVOFFH + BNA * ATSH)
#define ATT_SMEM ((PSOFFH + BMA * PSTH) * 2)   // 70656 B

__global__ void __launch_bounds__(256, 2) attn_kernel(
    const __nv_bfloat16* __restrict__ qkv, __nv_bfloat16* __restrict__ outp)
{
    extern __shared__ __align__(16) __nv_bfloat16 smh[];
    __nv_bfloat16* Qs = smh + QOFFH;
    __nv_bfloat16* KVs = smh + KVOFFH;
    __nv_bfloat16* Ps = smh + PSOFFH;
    uint32_t uQ = smem_u32(Qs), uKV = smem_u32(KVs), uP = smem_u32(Ps);

    int tid = threadIdx.x;
    int wid = tid >> 5, lane = tid & 31;
    int g = lane >> 2, q = lane & 3;
    int bh  = blockIdx.y;
    int m0  = blockIdx.x * BMA;
    int bb  = bh >> 3, hh = bh & 7;
    const __nv_bfloat16* base = qkv + (size_t)(bb * 1024 + hh * 128) * N3C;
    const int warpM = wid * 16;

    int a_r = (lane & 7) | (((lane >> 3) & 1) << 3);
    int a_c = (lane >> 4) << 3;
    int b_r = (lane & 7) | (((lane >> 4) & 1) << 3);
    int b_c = ((lane >> 3) & 1) << 3;
    int v_r = (lane & 7) | (((lane >> 3) & 1) << 3);
    int v_c = (lane >> 4) << 3;

    // Load Q tile: 128 rows x 16 chunks of 8 halves (raw-reshape gather)
    #pragma unroll
    for (int i = 0; i < 8; i++) {
        int f = i * 256 + tid;
        int r = f >> 4, c8 = f & 15;
        int l2 = m0 + r;
        const __nv_bfloat16* src = base + (size_t)(l2 >> 3) * N3C + ((l2 & 7) << 7) + c8 * 8;
        *(uint4*)&Qs[r * ATSH + c8 * 8] = *(const uint4*)src;
    }

    float Oacc[16][4];
    float lsum[2] = {0.f, 0.f};
    #pragma unroll
    for (int nt = 0; nt < 16; nt++)
        #pragma unroll
        for (int r = 0; r < 4; r++) Oacc[nt][r] = 0.f;

    for (int kt = 0; kt < NL / BNA; kt++) {
        int n0 = kt * BNA;
        __syncthreads();   // prev PV done with KVs/Ps; Q visible (1st iter)

        // K tile -> KVs (64 rows)
        #pragma unroll
        for (int i = 0; i < 4; i++) {
            int f = i * 256 + tid;
            int r = f >> 4, c8 = f & 15;
            int n = n0 + r;
            const __nv_bfloat16* src = base + (size_t)(n >> 3) * N3C + NC + ((n & 7) << 7) + c8 * 8;
            *(uint4*)&KVs[r * ATSH + c8 * 8] = *(const uint4*)src;
        }
        __syncthreads();

        // S = Q K^T : 8 ksteps of k16 over d=128
        float Sacc[8][4];
        #pragma unroll
        for (int nt = 0; nt < 8; nt++)
            #pragma unroll
            for (int r = 0; r < 4; r++) Sacc[nt][r] = 0.f;
        #pragma unroll
        for (int ks = 0; ks < 8; ks++) {
            int k0 = ks * 16;
            uint32_t afr[4], bfr[4][4];
            LDSM_X4(afr, uQ + (uint32_t)((warpM + a_r) * ATSH + k0 + a_c) * 2);
            #pragma unroll
            for (int np = 0; np < 4; np++)
                LDSM_X4(bfr[np], uKV + (uint32_t)((np * 16 + b_r) * ATSH + k0 + b_c) * 2);
            #pragma unroll
            for (int np = 0; np < 4; np++) {
                mma_bf16(Sacc[np * 2 + 0], afr, &bfr[np][0]);
                mma_bf16(Sacc[np * 2 + 1], afr, &bfr[np][2]);
            }
        }
        __syncthreads();   // done reading K

        // V tile -> KVs (64 rows)
        #pragma unroll
        for (int i = 0; i < 4; i++) {
            int f = i * 256 + tid;
            int r = f >> 4, c8 = f & 15;
            int n = n0 + r;
            const __nv_bfloat16* src = base + (size_t)(n >> 3) * N3C + 2 * NC + ((n & 7) << 7) + c8 * 8;
            *(uint4*)&KVs[r * ATSH + c8 * 8] = *(const uint4*)src;
        }

        // P = 2^S (log2-domain, no max), bf16 store, fp32 row sums
        #pragma unroll
        for (int h = 0; h < 2; h++) {
            float ls = 0.f;
            int prow = (warpM + g + 8 * h) * PSTH + 2 * q;
            #pragma unroll
            for (int nt = 0; nt < 8; nt++) {
                float e0 = ex2(Sacc[nt][2 * h + 0]);
                float e1 = ex2(Sacc[nt][2 * h + 1]);
                ls += e0 + e1;
                *reinterpret_cast<__nv_bfloat162*>(&Ps[prow + nt * 8]) =
                    __float22bfloat162_rn(make_float2(e0, e1));
            }
            ls += __shfl_xor_sync(0xffffffffu, ls, 1);
            ls += __shfl_xor_sync(0xffffffffu, ls, 2);
            lsum[h] += ls;
        }
        __syncthreads();   // V + P visible

        // O += P @ V : 4 ksteps of k16 over n=64; V via ldmatrix.trans
        #pragma unroll
        for (int kv = 0; kv < 4; kv++) {
            int k0 = kv * 16;
            uint32_t afr[4];
            LDSM_X4(afr, uP + (uint32_t)((warpM + a_r) * PSTH + k0 + a_c) * 2);
            #pragma unroll
            for (int dp = 0; dp < 8; dp++) {
                uint32_t vfr[4];
                LDSM_X4_T(vfr, uKV + (uint32_t)((k0 + v_r) * ATSH + dp * 16 + v_c) * 2);
                mma_bf16(Oacc[dp * 2 + 0], afr, &vfr[0]);
                mma_bf16(Oacc[dp * 2 + 1], afr, &vfr[2]);
            }
        }
    }

    // Epilogue: out = O / lsum, bf16 (flat layout == raw reshape back)
    #pragma unroll
    for (int h = 0; h < 2; h++) {
        float inv = 1.0f / lsum[h];
        int row = m0 + warpM + g + 8 * h;
        __nv_bfloat16* dst = outp + (size_t)bh * (NL * NCH) + (size_t)row * NCH + 2 * q;
        #pragma unroll
        for (int nt = 0; nt < 16; nt++) {
            float2 w;
            w.x = Oacc[nt][2 * h + 0] * inv;
            w.y = Oacc[nt][2 * h + 1] * inv;
            *reinterpret_cast<__nv_bfloat162*>(&dst[nt * 8]) = __float22bfloat162_rn(w);
        }
    }
}

// ---------------------------------------------------------------------------
extern "C" void kernel_launch(void* const* d_in, const int* in_sizes, int n_in,
                              void* d_out, int out_size)
{
    const float* x     = (const float*)d_in[0];
    const float* ln_g  = (const float*)d_in[1];
    const float* ln_b  = (const float*)d_in[2];
    const float* w_qkv = (const float*)d_in[3];
    const float* b_qkv = (const float*)d_in[4];
    const float* w_out = (const float*)d_in[5];
    const float* b_out = (const float*)d_in[6];
    float* out = (float*)d_out;

    float *xn;
    __nv_bfloat16 *xnh, *qkvb, *attnb, *wqkvh, *wouth;
    cudaGetSymbolAddress((void**)&xn,    g_xn);
    cudaGetSymbolAddress((void**)&xnh,   g_xnh);
    cudaGetSymbolAddress((void**)&qkvb,  g_qkv);
    cudaGetSymbolAddress((void**)&attnb, g_attn);
    cudaGetSymbolAddress((void**)&wqkvh, g_wqkvh);
    cudaGetSymbolAddress((void**)&wouth, g_wouth);

    cudaFuncSetAttribute(gemm_bf16_kernel<0>,
                         cudaFuncAttributeMaxDynamicSharedMemorySize, SMEM_GEMM);
    cudaFuncSetAttribute(gemm_bf16_kernel<1>,
                         cudaFuncAttributeMaxDynamicSharedMemorySize, SMEM_GEMM);
    cudaFuncSetAttribute(attn_kernel,
                         cudaFuncAttributeMaxDynamicSharedMemorySize, ATT_SMEM);

    // 0) Convert weights fp32 -> bf16 (native [K,N] layout, no transpose)
    cvt_kernel<<<(NC * N3C) / 2048, 256>>>(w_qkv, wqkvh);
    cvt_kernel<<<(NC * NC)  / 2048, 256>>>(w_out, wouth);

    // 1) LayerNorm (fp32 + bf16 outputs)
    ln_kernel<<<NB * NL, 256>>>(x, ln_g, ln_b, xn, xnh);

    // 2) QKV projection (bf16 mma; q cols pre-scaled by log2e) -> bf16
    gemm_bf16_kernel<0><<<dim3(N3C / BN, (NB * NL) / BM), 256, SMEM_GEMM>>>(
        xnh, wqkvh, b_qkv, nullptr, qkvb, N3C);

    // 3) Attention (bf16 mma, log2-domain no-max softmax) -> bf16
    attn_kernel<<<dim3(NL / BMA, NBH), 256, ATT_SMEM>>>(qkvb, attnb);

    // 4) Output projection + bias + residual(fp32 xn) -> fp32
    gemm_bf16_kernel<1><<<dim3(NC / BN, (NB * NL) / BM), 256, SMEM_GEMM>>>(
        attnb, wouth, b_out, xn, out, NC);
}

// round 11
// speedup vs baseline: 6.9375x; 1.0301x over previous
#include <cuda_runtime.h>
#include <cuda_bf16.h>
#include <cstdint>
#include <math.h>

// Problem dims
#define NB   8
#define NL   1024
#define NC   1024
#define NH   8
#define NCH  128
#define NBH  64
#define N3C  3072
#define QK_SCALE 0.29730177875068026f  // 128^(-1/4)
#define LOG2E    1.4426950408889634f

// Scratch (allocation-free rule: __device__ globals)
__device__ float          g_xn   [(size_t)NB * NL * NC];    // fp32 (residual)
__device__ __nv_bfloat16  g_xnh  [(size_t)NB * NL * NC];    // bf16 (GEMM A)
__device__ __nv_bfloat16  g_qkv  [(size_t)NB * NL * N3C];
__device__ __nv_bfloat16  g_attn [(size_t)NB * NL * NC];
__device__ __nv_bfloat16  g_wqkvh[(size_t)NC * N3C];        // bf16, native [K,N]
__device__ __nv_bfloat16  g_wouth[(size_t)NC * NC];         // bf16, native [K,N]

// ---------------------------------------------------------------------------
// Helpers (sm_80+ PTX only; target is plain compute_103 — no 'a' features)
// ---------------------------------------------------------------------------
__device__ __forceinline__ uint32_t smem_u32(const void* p) {
    uint32_t a;
    asm("{ .reg .u64 t; cvta.to.shared.u64 t, %1; cvt.u32.u64 %0, t; }" : "=r"(a) : "l"(p));
    return a;
}
__device__ __forceinline__ void cp16(uint32_t dst, const void* src) {
    asm volatile("cp.async.cg.shared.global [%0], [%1], 16;" :: "r"(dst), "l"(src));
}
#define CP_COMMIT() asm volatile("cp.async.commit_group;" ::: "memory")
#define CP_WAIT(n)  asm volatile("cp.async.wait_group %0;" :: "n"(n) : "memory")

__device__ __forceinline__ void mma_bf16(float* d, const uint32_t* a, const uint32_t* b) {
    asm volatile("mma.sync.aligned.m16n8k16.row.col.f32.bf16.bf16.f32 "
        "{%0,%1,%2,%3}, {%4,%5,%6,%7}, {%8,%9}, {%0,%1,%2,%3};"
        : "+f"(d[0]), "+f"(d[1]), "+f"(d[2]), "+f"(d[3])
        : "r"(a[0]), "r"(a[1]), "r"(a[2]), "r"(a[3]), "r"(b[0]), "r"(b[1]));
}
#define LDSM_X4(r, addr) \
    asm volatile("ldmatrix.sync.aligned.m8n8.x4.shared.b16 {%0,%1,%2,%3}, [%4];" \
        : "=r"((r)[0]), "=r"((r)[1]), "=r"((r)[2]), "=r"((r)[3]) : "r"(addr))
#define LDSM_X4_T(r, addr) \
    asm volatile("ldmatrix.sync.aligned.m8n8.x4.trans.shared.b16 {%0,%1,%2,%3}, [%4];" \
        : "=r"((r)[0]), "=r"((r)[1]), "=r"((r)[2]), "=r"((r)[3]) : "r"(addr))

__device__ __forceinline__ float ex2(float x) {
    float r;
    asm("ex2.approx.f32 %0, %1;" : "=f"(r) : "f"(x));
    return r;
}

// ---------------------------------------------------------------------------
// LayerNorm: fp32 out (residual) + bf16 out (GEMM operand)
// ---------------------------------------------------------------------------
__global__ void __launch_bounds__(256) ln_kernel(
    const float* __restrict__ x, const float* __restrict__ gamma,
    const float* __restrict__ beta, float* __restrict__ xn,
    __nv_bfloat16* __restrict__ xnh)
{
    int row = blockIdx.x;
    int t   = threadIdx.x;
    const float4* xr = reinterpret_cast<const float4*>(x + (size_t)row * NC);
    float4 v = xr[t];
    float s  = v.x + v.y + v.z + v.w;
    float ss = v.x*v.x + v.y*v.y + v.z*v.z + v.w*v.w;
    #pragma unroll
    for (int o = 16; o; o >>= 1) {
        s  += __shfl_xor_sync(0xffffffffu, s,  o);
        ss += __shfl_xor_sync(0xffffffffu, ss, o);
    }
    __shared__ float rs[8], rss[8], stat[2];
    int warp = t >> 5, lane = t & 31;
    if (lane == 0) { rs[warp] = s; rss[warp] = ss; }
    __syncthreads();
    if (t == 0) {
        float a = 0.f, b2 = 0.f;
        #pragma unroll
        for (int i = 0; i < 8; i++) { a += rs[i]; b2 += rss[i]; }
        float mu  = a * (1.0f / NC);
        float var = b2 * (1.0f / NC) - mu * mu;
        stat[0] = mu;
        stat[1] = rsqrtf(var + 1e-5f);
    }
    __syncthreads();
    float mu = stat[0], rstd = stat[1];
    float4 g4 = reinterpret_cast<const float4*>(gamma)[t];
    float4 b4 = reinterpret_cast<const float4*>(beta )[t];
    float4 o;
    o.x = (v.x - mu) * rstd * g4.x + b4.x;
    o.y = (v.y - mu) * rstd * g4.y + b4.y;
    o.z = (v.z - mu) * rstd * g4.z + b4.z;
    o.w = (v.w - mu) * rstd * g4.w + b4.w;
    reinterpret_cast<float4*>(xn + (size_t)row * NC)[t] = o;
    __nv_bfloat162 h0 = __float22bfloat162_rn(make_float2(o.x, o.y));
    __nv_bfloat162 h1 = __float22bfloat162_rn(make_float2(o.z, o.w));
    uint2 u; u.x = *(uint32_t*)&h0; u.y = *(uint32_t*)&h1;
    *reinterpret_cast<uint2*>(xnh + (size_t)row * NC + t * 4) = u;
}

// ---------------------------------------------------------------------------
// Elementwise fp32 -> bf16 convert (weights; layout preserved)
// ---------------------------------------------------------------------------
__global__ void __launch_bounds__(256) cvt_kernel(
    const float* __restrict__ src, __nv_bfloat16* __restrict__ dst)
{
    size_t i = ((size_t)blockIdx.x * 256 + threadIdx.x) * 8;
    float4 a = *(const float4*)(src + i);
    float4 b = *(const float4*)(src + i + 4);
    __nv_bfloat162 h0 = __float22bfloat162_rn(make_float2(a.x, a.y));
    __nv_bfloat162 h1 = __float22bfloat162_rn(make_float2(a.z, a.w));
    __nv_bfloat162 h2 = __float22bfloat162_rn(make_float2(b.x, b.y));
    __nv_bfloat162 h3 = __float22bfloat162_rn(make_float2(b.z, b.w));
    uint4 u;
    u.x = *(uint32_t*)&h0; u.y = *(uint32_t*)&h1;
    u.z = *(uint32_t*)&h2; u.w = *(uint32_t*)&h3;
    *reinterpret_cast<uint4*>(dst + i) = u;
}

// ---------------------------------------------------------------------------
// bf16 mma.sync GEMM: C[M,N] = A[M,K] @ B[K,N] (+bias; MODE epilogue)
// B native [K,N]; B frags via ldmatrix.trans. CTA 128x128, BK=64, 8 warps
// (2x4), warp 64x32, 3-stage cp.async, single barrier per chunk, and
// SOFTWARE-PIPELINED fragment double-buffering across k-steps.
// MODE 0: bf16 out, q cols *= QK_SCALE*LOG2E, k cols *= QK_SCALE.
// MODE 1: fp32 out, += bias + resid.
// ---------------------------------------------------------------------------
#define BM 128
#define BN 128
#define BK 64
#define KTOT 1024
#define NCHUNK (KTOT / BK)              // 16
#define GST 72                          // A smem halves stride (64+8)
#define BNS 136                         // B smem halves stride (128+8)
#define STAGE_H (BM * GST + BK * BNS)   // 17920 halves
#define SMEM_GEMM (3 * STAGE_H * 2)     // 107520 bytes

template <int MODE>
__global__ void __launch_bounds__(256, 2) gemm_bf16_kernel(
    const __nv_bfloat16* __restrict__ A, const __nv_bfloat16* __restrict__ Bw,
    const float* __restrict__ bias, const float* __restrict__ resid,
    void* __restrict__ Cm, int N)
{
    extern __shared__ __align__(16) __nv_bfloat16 smh[];
    uint32_t sbase = smem_u32(smh);
    int tid = threadIdx.x;
    int wid = tid >> 5, lane = tid & 31;
    int g = lane >> 2, q = lane & 3;
    const int bm = blockIdx.y * BM;
    const int bn = blockIdx.x * BN;
    const int warpM = (wid >> 2) * 64;
    const int warpN = (wid & 3) * 32;

    // ldmatrix lane address components
    int a_r = (lane & 7) | (((lane >> 3) & 1) << 3);   // A row within 16
    int a_c = (lane >> 4) << 3;                        // A k-halves offset
    int v_r = (lane & 7) | (((lane >> 3) & 1) << 3);   // B(k) row select
    int v_c = (lane >> 4) << 3;                        // B(n) +8 select

    auto load_chunk = [&](int kk, int stg) {
        uint32_t sA = sbase + (uint32_t)(stg * STAGE_H) * 2;
        uint32_t sB = sA + (uint32_t)(BM * GST) * 2;
        #pragma unroll
        for (int i = 0; i < 4; i++) {     // A: 128 rows x 8 chunks(8h)
            int f = i * 256 + tid;
            int r = f >> 3, c = f & 7;
            cp16(sA + (uint32_t)(r * GST + c * 8) * 2,
                 A + (size_t)(bm + r) * KTOT + kk + c * 8);
        }
        #pragma unroll
        for (int i = 0; i < 4; i++) {     // B: 64 k-rows x 16 chunks(8h)
            int f = i * 256 + tid;
            int r = f >> 4, c = f & 15;
            cp16(sB + (uint32_t)(r * BNS + c * 8) * 2,
                 Bw + (size_t)(kk + r) * N + bn + c * 8);
        }
        CP_COMMIT();
    };

    float accf[4][4][4];
    #pragma unroll
    for (int mt = 0; mt < 4; mt++)
        #pragma unroll
        for (int nt = 0; nt < 4; nt++)
            #pragma unroll
            for (int r = 0; r < 4; r++) accf[mt][nt][r] = 0.f;

    load_chunk(0, 0);
    load_chunk(BK, 1);

    for (int c = 0; c < NCHUNK; c++) {
        if (c < NCHUNK - 1) CP_WAIT(1); else CP_WAIT(0);
        __syncthreads();
        if (c + 2 < NCHUNK) load_chunk((c + 2) * BK, (c + 2) % 3);
        uint32_t sA = sbase + (uint32_t)((c % 3) * STAGE_H) * 2;
        uint32_t sB = sA + (uint32_t)(BM * GST) * 2;
        uint32_t aAddr = sA + (uint32_t)((warpM + a_r) * GST + a_c) * 2;
        uint32_t bAddr = sB + (uint32_t)(v_r * BNS + warpN + v_c) * 2;

        uint32_t afr[2][4][4], bfr[2][2][4];
        #pragma unroll
        for (int mt = 0; mt < 4; mt++)
            LDSM_X4(afr[0][mt], aAddr + (uint32_t)(mt * 16 * GST) * 2);
        #pragma unroll
        for (int np = 0; np < 2; np++)
            LDSM_X4_T(bfr[0][np], bAddr + (uint32_t)(np * 16) * 2);

        #pragma unroll
        for (int ks = 0; ks < 4; ks++) {
            int cur = ks & 1, nxt = cur ^ 1;
            if (ks < 3) {
                uint32_t aA = aAddr + (uint32_t)((ks + 1) * 16) * 2;
                uint32_t bA = bAddr + (uint32_t)((ks + 1) * 16 * BNS) * 2;
                #pragma unroll
                for (int mt = 0; mt < 4; mt++)
                    LDSM_X4(afr[nxt][mt], aA + (uint32_t)(mt * 16 * GST) * 2);
                #pragma unroll
                for (int np = 0; np < 2; np++)
                    LDSM_X4_T(bfr[nxt][np], bA + (uint32_t)(np * 16) * 2);
            }
            #pragma unroll
            for (int mt = 0; mt < 4; mt++)
                #pragma unroll
                for (int np = 0; np < 2; np++) {
                    mma_bf16(accf[mt][np * 2 + 0], afr[cur][mt], &bfr[cur][np][0]);
                    mma_bf16(accf[mt][np * 2 + 1], afr[cur][mt], &bfr[cur][np][2]);
                }
        }
    }

    #pragma unroll
    for (int mt = 0; mt < 4; mt++) {
        int row0 = bm + warpM + mt * 16 + g;
        #pragma unroll
        for (int nt = 0; nt < 4; nt++) {
            int col = bn + warpN + nt * 8 + q * 2;
            float2 bb = *(const float2*)&bias[col];
            float mscale = 1.0f;
            if (MODE == 0)
                mscale = (col < NC) ? (QK_SCALE * LOG2E)
                                    : ((col < 2 * NC) ? QK_SCALE : 1.0f);
            #pragma unroll
            for (int h = 0; h < 2; h++) {
                int row = row0 + h * 8;
                float2 o;
                o.x = accf[mt][nt][h * 2 + 0] + bb.x;
                o.y = accf[mt][nt][h * 2 + 1] + bb.y;
                if (MODE == 0) {
                    o.x *= mscale; o.y *= mscale;
                    __nv_bfloat162 hb = __float22bfloat162_rn(o);
                    *reinterpret_cast<__nv_bfloat162*>(
                        (__nv_bfloat16*)Cm + (size_t)row * N + col) = hb;
                } else {
                    float2 rr = *(const float2*)&resid[(size_t)row * NC + col];
                    o.x += rr.x; o.y += rr.y;
                    *reinterpret_cast<float2*>((float*)Cm + (size_t)row * N + col) = o;
                }
            }
        }
    }
}

// ---------------------------------------------------------------------------
// bf16 mma.sync flash attention, RAW-RESHAPED layout, no-max log2 softmax.
// BMA=128 q, BNA=64 kv, d=128. 256 threads = 8 warps x 16 m-rows.
// cp.async K/V/Q loads: K issued BEFORE the top barrier (no reader hazard),
// V in its own buffer loading behind the S-phase compute. 2 barriers + waits.
// ---------------------------------------------------------------------------
#define BMA 128
#define BNA 64
#define ATSH 136            // Q/K/V smem halves stride (128+8)
#define PSTH 72             // P smem halves stride (64+8)
#define QOFFH  0
#define KOFFH  (BMA * ATSH)            // 17408
#define VOFFH  (KOFFH + BNA * ATSH)    // 26112
#define PSOFFH (VOFFH + BNA * ATSH)    // 34816
#define ATT_SMEM ((PSOFFH + BMA * PSTH) * 2)   // 88064 B

__global__ void __launch_bounds__(256, 2) attn_kernel(
    const __nv_bfloat16* __restrict__ qkv, __nv_bfloat16* __restrict__ outp)
{
    extern __shared__ __align__(16) __nv_bfloat16 smh[];
    uint32_t uQ = smem_u32(smh + QOFFH);
    uint32_t uK = smem_u32(smh + KOFFH);
    uint32_t uV = smem_u32(smh + VOFFH);
    __nv_bfloat16* Ps = smh + PSOFFH;
    uint32_t uP = smem_u32(Ps);

    int tid = threadIdx.x;
    int wid = tid >> 5, lane = tid & 31;
    int g = lane >> 2, q = lane & 3;
    int bh  = blockIdx.y;
    int m0  = blockIdx.x * BMA;
    int bb  = bh >> 3, hh = bh & 7;
    const __nv_bfloat16* base = qkv + (size_t)(bb * 1024 + hh * 128) * N3C;
    const int warpM = wid * 16;

    int a_r = (lane & 7) | (((lane >> 3) & 1) << 3);
    int a_c = (lane >> 4) << 3;
    int b_r = (lane & 7) | (((lane >> 4) & 1) << 3);
    int b_c = ((lane >> 3) & 1) << 3;
    int v_r = (lane & 7) | (((lane >> 3) & 1) << 3);
    int v_c = (lane >> 4) << 3;

    // Q tile -> smem via cp.async (own group): 128 rows x 16 chunks of 8h
    #pragma unroll
    for (int i = 0; i < 8; i++) {
        int f = i * 256 + tid;
        int r = f >> 4, c8 = f & 15;
        int l2 = m0 + r;
        cp16(uQ + (uint32_t)(r * ATSH + c8 * 8) * 2,
             base + (size_t)(l2 >> 3) * N3C + ((l2 & 7) << 7) + c8 * 8);
    }
    CP_COMMIT();

    float Oacc[16][4];
    float lsum[2] = {0.f, 0.f};
    #pragma unroll
    for (int nt = 0; nt < 16; nt++)
        #pragma unroll
        for (int r = 0; r < 4; r++) Oacc[nt][r] = 0.f;

    for (int kt = 0; kt < NL / BNA; kt++) {
        int n0 = kt * BNA;

        // Issue K loads (Ks has no readers at this point — prior S-phase
        // reads all completed before the previous post-P barrier)
        #pragma unroll
        for (int i = 0; i < 4; i++) {
            int f = i * 256 + tid;
            int r = f >> 4, c8 = f & 15;
            int n = n0 + r;
            cp16(uK + (uint32_t)(r * ATSH + c8 * 8) * 2,
                 base + (size_t)(n >> 3) * N3C + NC + ((n & 7) << 7) + c8 * 8);
        }
        CP_COMMIT();

        __syncthreads();   // prev PV done (Vs, Ps free)

        // Issue V loads — land during the S-phase compute below
        #pragma unroll
        for (int i = 0; i < 4; i++) {
            int f = i * 256 + tid;
            int r = f >> 4, c8 = f & 15;
            int n = n0 + r;
            cp16(uV + (uint32_t)(r * ATSH + c8 * 8) * 2,
                 base + (size_t)(n >> 3) * N3C + 2 * NC + ((n & 7) << 7) + c8 * 8);
        }
        CP_COMMIT();

        CP_WAIT(1);        // K (and Q, first iter) arrived for this thread
        __syncthreads();   // ... and for all threads

        // S = Q K^T : 8 ksteps of k16 over d=128
        float Sacc[8][4];
        #pragma unroll
        for (int nt = 0; nt < 8; nt++)
            #pragma unroll
            for (int r = 0; r < 4; r++) Sacc[nt][r] = 0.f;
        #pragma unroll
        for (int ks = 0; ks < 8; ks++) {
            int k0 = ks * 16;
            uint32_t afr[4], bfr[4][4];
            LDSM_X4(afr, uQ + (uint32_t)((warpM + a_r) * ATSH + k0 + a_c) * 2);
            #pragma unroll
            for (int np = 0; np < 4; np++)
                LDSM_X4(bfr[np], uK + (uint32_t)((np * 16 + b_r) * ATSH + k0 + b_c) * 2);
            #pragma unroll
            for (int np = 0; np < 4; np++) {
                mma_bf16(Sacc[np * 2 + 0], afr, &bfr[np][0]);
                mma_bf16(Sacc[np * 2 + 1], afr, &bfr[np][2]);
            }
        }

        CP_WAIT(0);        // V arrived (this thread)

        // P = 2^S (log2-domain, no max), bf16 store, fp32 row sums
        #pragma unroll
        for (int h = 0; h < 2; h++) {
            float ls = 0.f;
            int prow = (warpM + g + 8 * h) * PSTH + 2 * q;
            #pragma unroll
            for (int nt = 0; nt < 8; nt++) {
                float e0 = ex2(Sacc[nt][2 * h + 0]);
                float e1 = ex2(Sacc[nt][2 * h + 1]);
                ls += e0 + e1;
                *reinterpret_cast<__nv_bfloat162*>(&Ps[prow + nt * 8]) =
                    __float22bfloat162_rn(make_float2(e0, e1));
            }
            ls += __shfl_xor_sync(0xffffffffu, ls, 1);
            ls += __shfl_xor_sync(0xffffffffu, ls, 2);
            lsum[h] += ls;
        }
        __syncthreads();   // P + V visible to all

        // O += P @ V : 4 ksteps of k16 over n=64; V via ldmatrix.trans
        #pragma unroll
        for (int kv = 0; kv < 4; kv++) {
            int k0 = kv * 16;
            uint32_t afr[4];
            LDSM_X4(afr, uP + (uint32_t)((warpM + a_r) * PSTH + k0 + a_c) * 2);
            #pragma unroll
            for (int dp = 0; dp < 8; dp++) {
                uint32_t vfr[4];
                LDSM_X4_T(vfr, uV + (uint32_t)((k0 + v_r) * ATSH + dp * 16 + v_c) * 2);
                mma_bf16(Oacc[dp * 2 + 0], afr, &vfr[0]);
                mma_bf16(Oacc[dp * 2 + 1], afr, &vfr[2]);
            }
        }
    }

    // Epilogue: out = O / lsum, bf16 (flat layout == raw reshape back)
    #pragma unroll
    for (int h = 0; h < 2; h++) {
        float inv = 1.0f / lsum[h];
        int row = m0 + warpM + g + 8 * h;
        __nv_bfloat16* dst = outp + (size_t)bh * (NL * NCH) + (size_t)row * NCH + 2 * q;
        #pragma unroll
        for (int nt = 0; nt < 16; nt++) {
            float2 w;
            w.x = Oacc[nt][2 * h + 0] * inv;
            w.y = Oacc[nt][2 * h + 1] * inv;
            *reinterpret_cast<__nv_bfloat162*>(&dst[nt * 8]) = __float22bfloat162_rn(w);
        }
    }
}

// ---------------------------------------------------------------------------
extern "C" void kernel_launch(void* const* d_in, const int* in_sizes, int n_in,
                              void* d_out, int out_size)
{
    const float* x     = (const float*)d_in[0];
    const float* ln_g  = (const float*)d_in[1];
    const float* ln_b  = (const float*)d_in[2];
    const float* w_qkv = (const float*)d_in[3];
    const float* b_qkv = (const float*)d_in[4];
    const float* w_out = (const float*)d_in[5];
    const float* b_out = (const float*)d_in[6];
    float* out = (float*)d_out;

    float *xn;
    __nv_bfloat16 *xnh, *qkvb, *attnb, *wqkvh, *wouth;
    cudaGetSymbolAddress((void**)&xn,    g_xn);
    cudaGetSymbolAddress((void**)&xnh,   g_xnh);
    cudaGetSymbolAddress((void**)&qkvb,  g_qkv);
    cudaGetSymbolAddress((void**)&attnb, g_attn);
    cudaGetSymbolAddress((void**)&wqkvh, g_wqkvh);
    cudaGetSymbolAddress((void**)&wouth, g_wouth);

    cudaFuncSetAttribute(gemm_bf16_kernel<0>,
                         cudaFuncAttributeMaxDynamicSharedMemorySize, SMEM_GEMM);
    cudaFuncSetAttribute(gemm_bf16_kernel<1>,
                         cudaFuncAttributeMaxDynamicSharedMemorySize, SMEM_GEMM);
    cudaFuncSetAttribute(attn_kernel,
                         cudaFuncAttributeMaxDynamicSharedMemorySize, ATT_SMEM);

    // 0) Convert weights fp32 -> bf16 (native [K,N] layout, no transpose)
    cvt_kernel<<<(NC * N3C) / 2048, 256>>>(w_qkv, wqkvh);
    cvt_kernel<<<(NC * NC)  / 2048, 256>>>(w_out, wouth);

    // 1) LayerNorm (fp32 + bf16 outputs)
    ln_kernel<<<NB * NL, 256>>>(x, ln_g, ln_b, xn, xnh);

    // 2) QKV projection (bf16 mma; q cols pre-scaled by log2e) -> bf16
    gemm_bf16_kernel<0><<<dim3(N3C / BN, (NB * NL) / BM), 256, SMEM_GEMM>>>(
        xnh, wqkvh, b_qkv, nullptr, qkvb, N3C);

    // 3) Attention (bf16 mma, log2-domain no-max softmax) -> bf16
    attn_kernel<<<dim3(NL / BMA, NBH), 256, ATT_SMEM>>>(qkvb, attnb);

    // 4) Output projection + bias + residual(fp32 xn) -> fp32
    gemm_bf16_kernel<1><<<dim3(NC / BN, (NB * NL) / BM), 256, SMEM_GEMM>>>(
        attnb, wouth, b_out, xn, out, NC);
}